// round 11
// baseline (speedup 1.0000x reference)
#include <cuda_runtime.h>
#include <cstdint>
#include <cstddef>

#define NB_ROWS 2048
#define NCOMBO  64
#define NSTRUCT 512
#define NHID    1024
#define NITER   60
#define PADNNZ  (NCOMBO * NSTRUCT + 2048)
#define SMNNZ   6144

// ---------------- device scratch ------------------------------------------
__device__ float g_C1[NB_ROWS * NHID];
__device__ float g_C2[NB_ROWS * NHID];
__device__ float g_Z [NB_ROWS * NSTRUCT];
__device__ int            g_row_ptr[NCOMBO + 1];             // x4-padded offsets
__device__ __align__(16) unsigned short g_csr_cols[PADNNZ];  // sentinel 512
__device__ int            g_col_ptr[NSTRUCT + 1];            // x4-padded offsets
__device__ __align__(16) unsigned short g_csc_rows[PADNNZ];  // sentinel 64
__device__ unsigned short g_sigc[NSTRUCT];                   // (level,warp) -> column
__device__ unsigned short g_sigr[NCOMBO];                    // (level,warp) -> row
__device__ float g_tau;

// ---------------- helpers -------------------------------------------------
__device__ __forceinline__ void cp_async16(void* smem, const void* gmem) {
    unsigned s = (unsigned)__cvta_generic_to_shared(smem);
    asm volatile("cp.async.cg.shared.global [%0], [%1], 16;\n" :: "r"(s), "l"(gmem));
}
__device__ __forceinline__ void cp_commit() { asm volatile("cp.async.commit_group;\n"); }
template<int N_> __device__ __forceinline__ void cp_wait() {
    asm volatile("cp.async.wait_group %0;\n" :: "n"(N_));
}

// ---------------- prep: x4-padded CSR/CSC, sig permutations, power iter ---
__global__ void prep_kernel(const float* __restrict__ S)
{
    __shared__ unsigned char s8[NCOMBO * NSTRUCT];
    __shared__ float v[NSTRUCT + 1];
    __shared__ float sv[NCOMBO + 1];
    __shared__ float red[16];
    __shared__ int   scnt[NCOMBO];
    __shared__ int   wtot[16];
    __shared__ short clen[NSTRUCT];

    const int t    = threadIdx.x;        // 512
    const int lane = t & 31;
    const int wid  = t >> 5;

    #pragma unroll 4
    for (int i = 0; i < NCOMBO; i++)
        s8[i * NSTRUCT + t] = (S[i * NSTRUCT + t] != 0.0f) ? 1 : 0;
    __syncthreads();

    // ---- CSR padded to x4, sentinel NSTRUCT ----
    if (t < NCOMBO) {
        int c = 0;
        for (int j = 0; j < NSTRUCT; j++) c += s8[t * NSTRUCT + j];
        scnt[t] = c;
    }
    __syncthreads();
    if (t == 0) {
        int acc = 0;
        for (int i = 0; i < NCOMBO; i++) { g_row_ptr[i] = acc; acc += (scnt[i] + 3) & ~3; }
        g_row_ptr[NCOMBO] = acc;
    }
    __syncthreads();
    if (t < NCOMBO) {
        int p = g_row_ptr[t];
        const int e = g_row_ptr[t + 1];
        for (int j = 0; j < NSTRUCT; j++)
            if (s8[t * NSTRUCT + j]) g_csr_cols[p++] = (unsigned short)j;
        while (p < e) g_csr_cols[p++] = (unsigned short)NSTRUCT;
    }

    // ---- CSC padded to x4, sentinel NCOMBO ----
    int cc = 0;
    for (int i = 0; i < NCOMBO; i++) cc += s8[i * NSTRUCT + t];
    clen[t] = (short)cc;
    const int pc = (cc + 3) & ~3;
    int incl = pc;
    #pragma unroll
    for (int o = 1; o < 32; o <<= 1) {
        int nbr = __shfl_up_sync(0xffffffffu, incl, o);
        if (lane >= o) incl += nbr;
    }
    if (lane == 31) wtot[wid] = incl;
    __syncthreads();
    if (t < 16) {
        int xv = wtot[t];
        #pragma unroll
        for (int o = 1; o < 16; o <<= 1) {
            int nbr = __shfl_up_sync(0x0000ffffu, xv, o);
            if (t >= o) xv += nbr;
        }
        wtot[t] = xv;
    }
    __syncthreads();
    {
        int base = (wid > 0) ? wtot[wid - 1] : 0;
        int cend = base + incl;
        g_col_ptr[t + 1] = cend;
        if (t == 0) g_col_ptr[0] = 0;
        int p = cend - pc;
        for (int i = 0; i < NCOMBO; i++)
            if (s8[i * NSTRUCT + t]) g_csc_rows[p++] = (unsigned short)i;
        while (p < cend) g_csc_rows[p++] = (unsigned short)NCOMBO;
    }
    __syncthreads();

    // ---- sigc: rank columns by length desc (index tiebreak), serpentine ----
    {
        const int mine = cc;
        int rank = 0;
        for (int c2 = 0; c2 < NSTRUCT; c2++) {
            const int l2 = clen[c2];
            rank += (l2 > mine) || (l2 == mine && c2 < t);
        }
        const int level = rank >> 5, pos = rank & 31;
        const int wv = (level & 1) ? (31 - pos) : pos;
        g_sigc[level * 32 + wv] = (unsigned short)t;
    }
    // ---- sigr: rank rows (64) desc, serpentine over 2 levels x 32 warps ----
    if (t < NCOMBO) {
        const int mine = scnt[t];
        int rank = 0;
        for (int r2 = 0; r2 < NCOMBO; r2++) {
            const int l2 = scnt[r2];
            rank += (l2 > mine) || (l2 == mine && r2 < t);
        }
        const int level = rank >> 5, pos = rank & 31;
        const int wv = (level & 1) ? (31 - pos) : pos;
        g_sigr[level * 32 + wv] = (unsigned short)t;
    }
    __syncthreads();

    // ---- power iteration (sentinels contribute 0) ----
    v[t] = 1.0f / sqrtf((float)NSTRUCT);
    if (t == 0) { v[NSTRUCT] = 0.f; sv[NCOMBO] = 0.f; }
    __syncthreads();
    for (int step = 0; step < 30; step++) {
        if (t < NCOMBO) {
            float a = 0.f;
            const int e = g_row_ptr[t + 1];
            for (int p = g_row_ptr[t]; p < e; p++) a += v[g_csr_cols[p]];
            sv[t] = a;
        }
        __syncthreads();
        float w = v[t];
        {
            const int e = g_col_ptr[t + 1];
            for (int p = g_col_ptr[t]; p < e; p++) w += sv[g_csc_rows[p]];
        }
        float sq = w * w;
        #pragma unroll
        for (int o = 16; o > 0; o >>= 1) sq += __shfl_xor_sync(0xffffffffu, sq, o);
        if (lane == 0) red[wid] = sq;
        __syncthreads();
        if (t == 0) {
            float s = 0.f;
            #pragma unroll
            for (int i = 0; i < 16; i++) s += red[i];
            red[0] = sqrtf(s);
        }
        __syncthreads();
        v[t] = w / red[0];
        __syncthreads();
    }
    if (t < NCOMBO) {
        float a = 0.f;
        const int e = g_row_ptr[t + 1];
        for (int p = g_row_ptr[t]; p < e; p++) a += v[g_csr_cols[p]];
        sv[t] = a;
    }
    __syncthreads();
    {
        float w = v[t];
        const int e = g_col_ptr[t + 1];
        for (int p = g_col_ptr[t]; p < e; p++) w += sv[g_csc_rows[p]];
        float sq = v[t] * w;
        #pragma unroll
        for (int o = 16; o > 0; o >>= 1) sq += __shfl_xor_sync(0xffffffffu, sq, o);
        if (lane == 0) red[wid] = sq;
        __syncthreads();
        if (t == 0) {
            float s = 0.f;
            #pragma unroll
            for (int i = 0; i < 16; i++) s += red[i];
            g_tau = 0.9f / sqrtf(s);
        }
    }
}

// ---------------- fp32 GEMM + bias + relu (R2 config, proven) -------------
template<int BM, int BN, int THREADS, int K, int N>
__device__ __forceinline__ void sgemm_v2(
    const float* __restrict__ A, const float* __restrict__ B,
    const float* __restrict__ bias, float* __restrict__ C)
{
    constexpr int KC = 16;
    constexpr int CA = BM * KC / 4;
    constexpr int CB = KC * BN / 4;
    constexpr int NSTAGE = K / KC;
    __shared__ float As[2][BM][KC];
    __shared__ float Bs[2][KC][BN];

    const int tid = threadIdx.x;
    const int m0  = blockIdx.y * BM;
    const int n0  = blockIdx.x * BN;
    constexpr int TX = BN / 8;
    const int tx = tid % TX;
    const int ty = tid / TX;
    const int rowA = ty * 4;
    const int colA = tx * 4;

    float acc[8][8];
    #pragma unroll
    for (int i = 0; i < 8; i++)
        #pragma unroll
        for (int j = 0; j < 8; j++) acc[i][j] = 0.f;

    {
        #pragma unroll
        for (int c = tid; c < CA; c += THREADS) {
            int m  = c >> 2;
            int kq = (c & 3) * 4;
            cp_async16(&As[0][m][kq], A + (size_t)(m0 + m) * K + kq);
        }
        #pragma unroll
        for (int c = tid; c < CB; c += THREADS) {
            int kr = c / (BN / 4);
            int nq = (c % (BN / 4)) * 4;
            cp_async16(&Bs[0][kr][nq], B + (size_t)kr * N + n0 + nq);
        }
        cp_commit();
    }

    for (int s = 0; s < NSTAGE; s++) {
        if (s + 1 < NSTAGE) {
            const int k0 = (s + 1) * KC;
            const int nb = (s + 1) & 1;
            #pragma unroll
            for (int c = tid; c < CA; c += THREADS) {
                int m  = c >> 2;
                int kq = (c & 3) * 4;
                cp_async16(&As[nb][m][kq], A + (size_t)(m0 + m) * K + k0 + kq);
            }
            #pragma unroll
            for (int c = tid; c < CB; c += THREADS) {
                int kr = c / (BN / 4);
                int nq = (c % (BN / 4)) * 4;
                cp_async16(&Bs[nb][kr][nq], B + (size_t)(k0 + kr) * N + n0 + nq);
            }
            cp_commit();
            cp_wait<1>();
        } else {
            cp_wait<0>();
        }
        __syncthreads();
        const int buf = s & 1;
        #pragma unroll
        for (int kk = 0; kk < KC; kk++) {
            float fa[8], fb[8];
            #pragma unroll
            for (int i = 0; i < 4; i++) {
                fa[i]     = As[buf][rowA + i][kk];
                fa[4 + i] = As[buf][rowA + BM / 2 + i][kk];
            }
            *(float4*)&fb[0] = *(const float4*)&Bs[buf][kk][colA];
            *(float4*)&fb[4] = *(const float4*)&Bs[buf][kk][colA + BN / 2];
            #pragma unroll
            for (int i = 0; i < 8; i++)
                #pragma unroll
                for (int j = 0; j < 8; j++)
                    acc[i][j] = fmaf(fa[i], fb[j], acc[i][j]);
        }
        __syncthreads();
    }

    float4 bl = *(const float4*)(bias + n0 + colA);
    float4 bh = *(const float4*)(bias + n0 + colA + BN / 2);
    #pragma unroll
    for (int half = 0; half < 2; half++) {
        #pragma unroll
        for (int i = 0; i < 4; i++) {
            const int m  = m0 + rowA + half * (BM / 2) + i;
            const int ai = half * 4 + i;
            float4 o;
            o.x = fmaxf(acc[ai][0] + bl.x, 0.f);
            o.y = fmaxf(acc[ai][1] + bl.y, 0.f);
            o.z = fmaxf(acc[ai][2] + bl.z, 0.f);
            o.w = fmaxf(acc[ai][3] + bl.w, 0.f);
            *(float4*)(C + (size_t)m * N + n0 + colA) = o;
            float4 p;
            p.x = fmaxf(acc[ai][4] + bh.x, 0.f);
            p.y = fmaxf(acc[ai][5] + bh.y, 0.f);
            p.z = fmaxf(acc[ai][6] + bh.z, 0.f);
            p.w = fmaxf(acc[ai][7] + bh.w, 0.f);
            *(float4*)(C + (size_t)m * N + n0 + colA + BN / 2) = p;
        }
    }
}

__global__ __launch_bounds__(256, 2) void gemm1_kernel(
    const float* __restrict__ X, const float* __restrict__ W1, const float* __restrict__ b1)
{ sgemm_v2<128, 128, 256, NCOMBO, NHID>(X, W1, b1, g_C1); }

__global__ __launch_bounds__(256, 2) void gemm2_kernel(
    const float* __restrict__ W2, const float* __restrict__ b2)
{ sgemm_v2<128, 128, 256, NHID, NHID>(g_C1, W2, b2, g_C2); }

__global__ __launch_bounds__(128, 2) void gemm3_kernel(
    const float* __restrict__ W3, const float* __restrict__ b3)
{ sgemm_v2<64, 128, 128, NHID, NSTRUCT>(g_C2, W3, b3, g_Z); }

// ---------------- PDHG v6: warp-uniform gathers, 64 CTAs x 1024 threads ---
// lane = batch row (32/CTA); warp w owns 2 head rows (sigr) + 16 columns (sigc).
// Every smem gather: uniform index, 32 consecutive floats -> 1 phase.
#define PD_XBAR   0
#define PD_YHEAD  (PD_XBAR + (NSTRUCT + 1) * 32 * 4)       // 65664
#define PD_RED    (PD_YHEAD + (NCOMBO + 1) * 32 * 4)       // +8320
#define PD_RP     (PD_RED + 32 * 32 * 4)                   // +4096
#define PD_CP     (PD_RP + ((NCOMBO + 2) & ~1) * 4)
#define PD_SIGC   (PD_CP + ((NSTRUCT + 2) & ~1) * 4)
#define PD_SIGR   (PD_SIGC + NSTRUCT * 2)
#define PD_CSR    ((PD_SIGR + NCOMBO * 2 + 15) & ~15)
#define PD_CSC    (PD_CSR + SMNNZ * 2)
#define PD_SMEM   (PD_CSC + SMNNZ * 2)

__global__ __launch_bounds__(1024, 1) void pdhg_kernel(
    const float* __restrict__ Xg, float* __restrict__ out)
{
    extern __shared__ char smem[];
    float* s_xbar  = (float*)(smem + PD_XBAR);
    float* s_yhead = (float*)(smem + PD_YHEAD);
    float* s_red   = (float*)(smem + PD_RED);
    int*   s_rp    = (int*)  (smem + PD_RP);
    int*   s_cp    = (int*)  (smem + PD_CP);
    unsigned short* s_sigc = (unsigned short*)(smem + PD_SIGC);
    unsigned short* s_sigr = (unsigned short*)(smem + PD_SIGR);
    unsigned short* s_csr  = (unsigned short*)(smem + PD_CSR);
    unsigned short* s_csc  = (unsigned short*)(smem + PD_CSC);

    const int tid  = threadIdx.x;
    const int lane = tid & 31;
    const int w    = tid >> 5;      // 0..31
    const int brow = blockIdx.x * 32 + lane;

    for (int p = tid; p < NCOMBO + 1;  p += 1024) s_rp[p] = g_row_ptr[p];
    for (int p = tid; p < NSTRUCT + 1; p += 1024) s_cp[p] = g_col_ptr[p];
    for (int p = tid; p < NSTRUCT;     p += 1024) s_sigc[p] = g_sigc[p];
    for (int p = tid; p < NCOMBO;      p += 1024) s_sigr[p] = g_sigr[p];
    for (int p = tid; p < (NSTRUCT + 1) * 32; p += 1024) s_xbar[p] = 0.f;
    for (int p = tid; p < (NCOMBO + 1) * 32;  p += 1024) s_yhead[p] = 0.f;
    __syncthreads();
    const int nnzr = s_rp[NCOMBO];
    const int nnzc = s_cp[NSTRUCT];
    const bool fits = (nnzr <= SMNNZ) && (nnzc <= SMNNZ);
    if (fits) {
        for (int p = tid; p < nnzr; p += 1024) s_csr[p] = g_csr_cols[p];
        for (int p = tid; p < nnzc; p += 1024) s_csc[p] = g_csc_rows[p];
    }
    __syncthreads();
    const ushort4* __restrict__ csr4 =
        fits ? (const ushort4*)s_csr : (const ushort4*)g_csr_cols;
    const ushort4* __restrict__ csc4 =
        fits ? (const ushort4*)s_csc : (const ushort4*)g_csc_rows;
    const float tau = g_tau;

    // per-thread state: 16 columns (jc), 2 head rows
    int   jc[16];
    float x[16], z[16], yt[16];
    #pragma unroll
    for (int lv = 0; lv < 16; lv++) {
        const int j = s_sigc[lv * 32 + w];
        jc[lv] = j;
        z[lv]  = g_Z[(size_t)brow * NSTRUCT + j];
        x[lv]  = 0.f;
        yt[lv] = 0.f;
    }
    const int ra = s_sigr[w];
    const int rb = s_sigr[32 + w];
    const float Bva = Xg[(size_t)brow * NCOMBO + ra];
    const float Bvb = Xg[(size_t)brow * NCOMBO + rb];
    float yha = 0.f, yhb = 0.f;
    const int ras = s_rp[ra] >> 2, rae = s_rp[ra + 1] >> 2;
    const int rbs = s_rp[rb] >> 2, rbe = s_rp[rb + 1] >> 2;
    __syncthreads();

    for (int it = 0; it < NITER; it++) {
        // ---- phase A: 2 head rows per warp, warp-uniform gathers ----
        {
            float a0 = 0.f, a1 = 0.f, a2 = 0.f, a3 = 0.f;
            for (int p = ras; p < rae; p++) {
                const ushort4 c = csr4[p];
                a0 += s_xbar[c.x * 32 + lane];
                a1 += s_xbar[c.y * 32 + lane];
                a2 += s_xbar[c.z * 32 + lane];
                a3 += s_xbar[c.w * 32 + lane];
            }
            yha = fmaxf(fmaf(tau, ((a0 + a1) + (a2 + a3)) - Bva, yha), 0.f);
            s_yhead[ra * 32 + lane] = yha;
        }
        {
            float a0 = 0.f, a1 = 0.f, a2 = 0.f, a3 = 0.f;
            for (int p = rbs; p < rbe; p++) {
                const ushort4 c = csr4[p];
                a0 += s_xbar[c.x * 32 + lane];
                a1 += s_xbar[c.y * 32 + lane];
                a2 += s_xbar[c.z * 32 + lane];
                a3 += s_xbar[c.w * 32 + lane];
            }
            yhb = fmaxf(fmaf(tau, ((a0 + a1) + (a2 + a3)) - Bvb, yhb), 0.f);
            s_yhead[rb * 32 + lane] = yhb;
        }
        __syncthreads();

        // ---- phase B: 16 columns per warp; d kept in registers ----
        float d[16];
        float ss = 0.f;
        #pragma unroll
        for (int lv = 0; lv < 16; lv++) {
            const int j = jc[lv];
            const float xbo = s_xbar[j * 32 + lane];
            yt[lv] = fmaxf(fmaf(-tau, xbo, yt[lv]), 0.f);
            float t0 = 0.f, t1 = 0.f, t2 = 0.f, t3 = 0.f;
            const int ps = s_cp[j] >> 2, pe = s_cp[j + 1] >> 2;
            for (int p = ps; p < pe; p++) {
                const ushort4 rr = csc4[p];
                t0 += s_yhead[rr.x * 32 + lane];
                t1 += s_yhead[rr.y * 32 + lane];
                t2 += s_yhead[rr.z * 32 + lane];
                t3 += s_yhead[rr.w * 32 + lane];
            }
            const float tv = ((t0 + t1) + (t2 + t3)) - yt[lv];
            const float dd = fmaf(-tau, tv, x[lv]) + tau - z[lv];
            d[lv] = dd;
            ss += dd * dd;
        }
        s_red[w * 32 + lane] = ss;
        __syncthreads();

        // ---- phase C: norm -> scale -> x / xbar update ----
        float tot = 0.f;
        #pragma unroll
        for (int w2 = 0; w2 < 32; w2++) tot += s_red[w2 * 32 + lane];
        const float sc = fmaxf(1.f - tau / fmaxf(sqrtf(tot), 1e-12f), 0.f);
        #pragma unroll
        for (int lv = 0; lv < 16; lv++) {
            const float xn = fmaf(sc, d[lv], z[lv]);
            s_xbar[jc[lv] * 32 + lane] = 2.f * xn - x[lv];
            x[lv] = xn;
        }
        __syncthreads();
    }

    #pragma unroll
    for (int lv = 0; lv < 16; lv++)
        out[(size_t)brow * NSTRUCT + jc[lv]] = x[lv];
}

// ---------------- launch -------------------------------------------------
extern "C" void kernel_launch(void* const* d_in, const int* in_sizes, int n_in,
                              void* d_out, int out_size)
{
    const float* X  = (const float*)d_in[0];
    const float* W1 = (const float*)d_in[1];
    const float* b1 = (const float*)d_in[2];
    const float* W2 = (const float*)d_in[3];
    const float* b2 = (const float*)d_in[4];
    const float* W3 = (const float*)d_in[5];
    const float* b3 = (const float*)d_in[6];
    const float* S  = (const float*)d_in[7];
    float* out = (float*)d_out;

    cudaFuncSetAttribute(pdhg_kernel,
                         cudaFuncAttributeMaxDynamicSharedMemorySize, PD_SMEM);

    prep_kernel<<<1, 512>>>(S);

    gemm1_kernel<<<dim3(NHID / 128,    NB_ROWS / 128), 256>>>(X, W1, b1);
    gemm2_kernel<<<dim3(NHID / 128,    NB_ROWS / 128), 256>>>(W2, b2);
    gemm3_kernel<<<dim3(NSTRUCT / 128, NB_ROWS / 64),  128>>>(W3, b3);

    pdhg_kernel<<<NB_ROWS / 32, 1024, PD_SMEM>>>(X, out);
}

// round 12
// speedup vs baseline: 1.6051x; 1.6051x over previous
#include <cuda_runtime.h>
#include <cstdint>
#include <cstddef>

#define NB_ROWS 2048
#define NCOMBO  64
#define NSTRUCT 512
#define NHID    1024
#define NITER   60
#define MAXNNZ  (NCOMBO * NSTRUCT)
#define SMNNZ   4096

// ---------------- device scratch ------------------------------------------
__device__ float g_C1[NB_ROWS * NHID];
__device__ float g_C2[NB_ROWS * NHID];
__device__ float g_Z [NB_ROWS * NSTRUCT];
__device__ int            g_row_ptr[NCOMBO + 1];
__device__ unsigned short g_csr_cols[MAXNNZ];
__device__ int            g_col_ptr[NSTRUCT + 1];
__device__ unsigned short g_csc_rows[MAXNNZ];
__device__ float g_tau;

// ---------------- helpers -------------------------------------------------
__device__ __forceinline__ void cp_async16(void* smem, const void* gmem) {
    unsigned s = (unsigned)__cvta_generic_to_shared(smem);
    asm volatile("cp.async.cg.shared.global [%0], [%1], 16;\n" :: "r"(s), "l"(gmem));
}
__device__ __forceinline__ void cp_commit() { asm volatile("cp.async.commit_group;\n"); }
template<int N_> __device__ __forceinline__ void cp_wait() {
    asm volatile("cp.async.wait_group %0;\n" :: "n"(N_));
}

// ---------------- prep: CSR/CSC of S + smem power iteration -> g_tau -----
__global__ void prep_kernel(const float* __restrict__ S)
{
    __shared__ unsigned char s8[NCOMBO * NSTRUCT];   // 32KB; reused for lists
    __shared__ float v[NSTRUCT];
    __shared__ float sv[NCOMBO];
    __shared__ float red[16];
    __shared__ int   scnt[NCOMBO];
    __shared__ int   wtot[16];
    __shared__ int   srp[NCOMBO + 1];
    __shared__ int   scp[NSTRUCT + 1];

    const int t    = threadIdx.x;        // 512
    const int lane = t & 31;
    const int wid  = t >> 5;

    #pragma unroll 4
    for (int i = 0; i < NCOMBO; i++)
        s8[i * NSTRUCT + t] = (S[i * NSTRUCT + t] != 0.0f) ? 1 : 0;
    __syncthreads();

    // ---- CSR ----
    if (t < NCOMBO) {
        int c = 0;
        for (int j = 0; j < NSTRUCT; j++) c += s8[t * NSTRUCT + j];
        scnt[t] = c;
    }
    __syncthreads();
    if (t == 0) {
        int acc = 0;
        for (int i = 0; i < NCOMBO; i++) { g_row_ptr[i] = acc; srp[i] = acc; acc += scnt[i]; }
        g_row_ptr[NCOMBO] = acc; srp[NCOMBO] = acc;
    }
    __syncthreads();
    if (t < NCOMBO) {
        int p = srp[t];
        for (int j = 0; j < NSTRUCT; j++)
            if (s8[t * NSTRUCT + j]) g_csr_cols[p++] = (unsigned short)j;
    }

    // ---- CSC via block scan ----
    int cc = 0;
    for (int i = 0; i < NCOMBO; i++) cc += s8[i * NSTRUCT + t];
    int incl = cc;
    #pragma unroll
    for (int o = 1; o < 32; o <<= 1) {
        int nbr = __shfl_up_sync(0xffffffffu, incl, o);
        if (lane >= o) incl += nbr;
    }
    if (lane == 31) wtot[wid] = incl;
    __syncthreads();
    if (t < 16) {
        int xv = wtot[t];
        #pragma unroll
        for (int o = 1; o < 16; o <<= 1) {
            int nbr = __shfl_up_sync(0x0000ffffu, xv, o);
            if (t >= o) xv += nbr;
        }
        wtot[t] = xv;
    }
    __syncthreads();
    {
        int base = (wid > 0) ? wtot[wid - 1] : 0;
        int cend = base + incl;
        g_col_ptr[t + 1] = cend; scp[t + 1] = cend;
        if (t == 0) { g_col_ptr[0] = 0; scp[0] = 0; }
        int p = cend - cc;
        for (int i = 0; i < NCOMBO; i++)
            if (s8[i * NSTRUCT + t]) g_csc_rows[p++] = (unsigned short)i;
    }
    __syncthreads();

    // ---- overlay lists into smem (s8 dead from here) ----
    unsigned short* sl_csr = (unsigned short*)s8;             // 8192 entries
    unsigned short* sl_csc = (unsigned short*)(s8 + 16384);   // 8192 entries
    const int nr = srp[NCOMBO];
    const int nc = scp[NSTRUCT];
    const bool ok = (nr <= 8192) && (nc <= 8192);
    if (ok) {
        for (int p = t; p < nr; p += 512) sl_csr[p] = g_csr_cols[p];
        for (int p = t; p < nc; p += 512) sl_csc[p] = g_csc_rows[p];
    }
    __syncthreads();
    const unsigned short* __restrict__ pcsr = ok ? sl_csr : g_csr_cols;
    const unsigned short* __restrict__ pcsc = ok ? sl_csc : g_csc_rows;

    // ---- power iteration on S^T S + I (all-smem) ----
    v[t] = 1.0f / sqrtf((float)NSTRUCT);
    __syncthreads();
    for (int step = 0; step < 30; step++) {
        if (t < NCOMBO) {
            float a = 0.f;
            const int e = srp[t + 1];
            for (int p = srp[t]; p < e; p++) a += v[pcsr[p]];
            sv[t] = a;
        }
        __syncthreads();
        float w = v[t];
        {
            const int e = scp[t + 1];
            for (int p = scp[t]; p < e; p++) w += sv[pcsc[p]];
        }
        float sq = w * w;
        #pragma unroll
        for (int o = 16; o > 0; o >>= 1) sq += __shfl_xor_sync(0xffffffffu, sq, o);
        if (lane == 0) red[wid] = sq;
        __syncthreads();
        if (t == 0) {
            float s = 0.f;
            #pragma unroll
            for (int i = 0; i < 16; i++) s += red[i];
            red[0] = sqrtf(s);
        }
        __syncthreads();
        v[t] = w / red[0];
        __syncthreads();
    }
    if (t < NCOMBO) {
        float a = 0.f;
        const int e = srp[t + 1];
        for (int p = srp[t]; p < e; p++) a += v[pcsr[p]];
        sv[t] = a;
    }
    __syncthreads();
    {
        float w = v[t];
        const int e = scp[t + 1];
        for (int p = scp[t]; p < e; p++) w += sv[pcsc[p]];
        float sq = v[t] * w;
        #pragma unroll
        for (int o = 16; o > 0; o >>= 1) sq += __shfl_xor_sync(0xffffffffu, sq, o);
        if (lane == 0) red[wid] = sq;
        __syncthreads();
        if (t == 0) {
            float s = 0.f;
            #pragma unroll
            for (int i = 0; i < 16; i++) s += red[i];
            g_tau = 0.9f / sqrtf(s);
        }
    }
}

// ---------------- sgemm_v3: transposed-A smem, float4 inner loop ----------
// As[KC][BM] (staged LDG->reg->STS), Bs[KC][BN] (cp.async). Inner loop per kk:
// 2 LDS.128 (A) + 2 LDS.128 (B) + 64 FFMA.
template<int BM, int BN, int THREADS, int K, int N>
__device__ __forceinline__ void sgemm_v3(
    const float* __restrict__ A, const float* __restrict__ B,
    const float* __restrict__ bias, float* __restrict__ C)
{
    constexpr int KC = 16;
    constexpr int CA4 = BM * KC / 4 / THREADS;   // float4 A-loads per thread
    constexpr int CB  = KC * BN / 4;
    constexpr int NSTAGE = K / KC;
    __shared__ float As[2][KC][BM];
    __shared__ float Bs[2][KC][BN];

    const int tid = threadIdx.x;
    const int m0  = blockIdx.y * BM;
    const int n0  = blockIdx.x * BN;
    constexpr int TX = BN / 8;
    const int tx = tid % TX;
    const int ty = tid / TX;
    const int rowA = ty * 4;
    const int colA = tx * 4;

    float acc[8][8];
    #pragma unroll
    for (int i = 0; i < 8; i++)
        #pragma unroll
        for (int j = 0; j < 8; j++) acc[i][j] = 0.f;

    // A loader coords (per q): c = tid + q*THREADS, m = c>>2, kq = (c&3)*4
    int am[CA4], akq[CA4];
    #pragma unroll
    for (int q = 0; q < CA4; q++) {
        const int c = tid + q * THREADS;
        am[q]  = c >> 2;
        akq[q] = (c & 3) * 4;
    }

    float4 areg[CA4];
    // prologue: A(0) -> regs, B(0) -> cp.async
    #pragma unroll
    for (int q = 0; q < CA4; q++)
        areg[q] = *(const float4*)(A + (size_t)(m0 + am[q]) * K + akq[q]);
    #pragma unroll
    for (int c = tid; c < CB; c += THREADS) {
        const int kr = c / (BN / 4);
        const int nq = (c % (BN / 4)) * 4;
        cp_async16(&Bs[0][kr][nq], B + (size_t)kr * N + n0 + nq);
    }
    cp_commit();

    for (int s = 0; s < NSTAGE; s++) {
        const int buf = s & 1;
        // STS A(s) (buffer free: guaranteed by barrier at end of prev iter)
        #pragma unroll
        for (int q = 0; q < CA4; q++) {
            As[buf][akq[q] + 0][am[q]] = areg[q].x;
            As[buf][akq[q] + 1][am[q]] = areg[q].y;
            As[buf][akq[q] + 2][am[q]] = areg[q].z;
            As[buf][akq[q] + 3][am[q]] = areg[q].w;
        }
        if (s + 1 < NSTAGE) {
            const int k0 = (s + 1) * KC;
            const int nb = (s + 1) & 1;
            #pragma unroll
            for (int c = tid; c < CB; c += THREADS) {
                const int kr = c / (BN / 4);
                const int nq = (c % (BN / 4)) * 4;
                cp_async16(&Bs[nb][kr][nq], B + (size_t)(k0 + kr) * N + n0 + nq);
            }
            cp_commit();
            cp_wait<1>();
        } else {
            cp_wait<0>();
        }
        __syncthreads();
        if (s + 1 < NSTAGE) {
            const int k0 = (s + 1) * KC;
            #pragma unroll
            for (int q = 0; q < CA4; q++)
                areg[q] = *(const float4*)(A + (size_t)(m0 + am[q]) * K + k0 + akq[q]);
        }
        #pragma unroll
        for (int kk = 0; kk < KC; kk++) {
            float fa[8], fb[8];
            *(float4*)&fa[0] = *(const float4*)&As[buf][kk][rowA];
            *(float4*)&fa[4] = *(const float4*)&As[buf][kk][rowA + BM / 2];
            *(float4*)&fb[0] = *(const float4*)&Bs[buf][kk][colA];
            *(float4*)&fb[4] = *(const float4*)&Bs[buf][kk][colA + BN / 2];
            #pragma unroll
            for (int i = 0; i < 8; i++)
                #pragma unroll
                for (int j = 0; j < 8; j++)
                    acc[i][j] = fmaf(fa[i], fb[j], acc[i][j]);
        }
        __syncthreads();
    }

    float4 bl = *(const float4*)(bias + n0 + colA);
    float4 bh = *(const float4*)(bias + n0 + colA + BN / 2);
    #pragma unroll
    for (int half = 0; half < 2; half++) {
        #pragma unroll
        for (int i = 0; i < 4; i++) {
            const int m  = m0 + rowA + half * (BM / 2) + i;
            const int ai = half * 4 + i;
            float4 o;
            o.x = fmaxf(acc[ai][0] + bl.x, 0.f);
            o.y = fmaxf(acc[ai][1] + bl.y, 0.f);
            o.z = fmaxf(acc[ai][2] + bl.z, 0.f);
            o.w = fmaxf(acc[ai][3] + bl.w, 0.f);
            *(float4*)(C + (size_t)m * N + n0 + colA) = o;
            float4 p;
            p.x = fmaxf(acc[ai][4] + bh.x, 0.f);
            p.y = fmaxf(acc[ai][5] + bh.y, 0.f);
            p.z = fmaxf(acc[ai][6] + bh.z, 0.f);
            p.w = fmaxf(acc[ai][7] + bh.w, 0.f);
            *(float4*)(C + (size_t)m * N + n0 + colA + BN / 2) = p;
        }
    }
}

__global__ __launch_bounds__(256, 2) void gemm1_kernel(
    const float* __restrict__ X, const float* __restrict__ W1, const float* __restrict__ b1)
{ sgemm_v3<128, 128, 256, NCOMBO, NHID>(X, W1, b1, g_C1); }

__global__ __launch_bounds__(256, 2) void gemm2_kernel(
    const float* __restrict__ W2, const float* __restrict__ b2)
{ sgemm_v3<128, 128, 256, NHID, NHID>(g_C1, W2, b2, g_C2); }

__global__ __launch_bounds__(128, 2) void gemm3_kernel(
    const float* __restrict__ W3, const float* __restrict__ b3)
{ sgemm_v3<64, 128, 128, NHID, NSTRUCT>(g_C2, W3, b3, g_Z); }

// ---------------- PDHG: exact R2 (8 rows/CTA, float2 over batch) ----------
__global__ __launch_bounds__(256, 2) void pdhg_kernel(
    const float* __restrict__ Xg, float* __restrict__ out)
{
    __shared__ float s_xbar[NSTRUCT * 8];
    __shared__ float s_yhead[NCOMBO * 8];
    __shared__ unsigned short s_csr[SMNNZ];
    __shared__ unsigned short s_csc[SMNNZ];
    __shared__ int    s_rp[NCOMBO + 1];
    __shared__ int    s_cp[NSTRUCT + 1];
    __shared__ float2 s_red[8][4];

    const int tid = threadIdx.x;
    const int b2  = tid & 3;
    const int dl  = tid >> 2;
    const int wid = tid >> 5;
    const int r0  = blockIdx.x * 8 + b2 * 2;

    for (int p = tid; p < NCOMBO + 1;  p += 256) s_rp[p] = g_row_ptr[p];
    for (int p = tid; p < NSTRUCT + 1; p += 256) s_cp[p] = g_col_ptr[p];
    __syncthreads();
    const int nnz = s_rp[NCOMBO];
    for (int p = tid; p < nnz && p < SMNNZ; p += 256) {
        s_csr[p] = g_csr_cols[p];
        s_csc[p] = g_csc_rows[p];
    }
    const unsigned short* __restrict__ csr = (nnz <= SMNNZ) ? s_csr : g_csr_cols;
    const unsigned short* __restrict__ csc = (nnz <= SMNNZ) ? s_csc : g_csc_rows;
    const float tau = g_tau;

    float2 x[8], z[8], yt[8], xb[8];
    #pragma unroll
    for (int k = 0; k < 8; k++) {
        const int j = k * 64 + dl;
        z[k].x = g_Z[(size_t)r0 * NSTRUCT + j];
        z[k].y = g_Z[(size_t)(r0 + 1) * NSTRUCT + j];
        x[k]  = make_float2(0.f, 0.f);
        yt[k] = make_float2(0.f, 0.f);
        xb[k] = make_float2(0.f, 0.f);
        *(float2*)&s_xbar[j * 8 + b2 * 2] = make_float2(0.f, 0.f);
    }
    const int i = dl;
    float2 Bv = make_float2(Xg[(size_t)r0 * NCOMBO + i],
                            Xg[(size_t)(r0 + 1) * NCOMBO + i]);
    float2 yh = make_float2(0.f, 0.f);
    const int rs = s_rp[i], re = s_rp[i + 1];
    __syncthreads();

    for (int it = 0; it < NITER; it++) {
        float2 a = make_float2(0.f, 0.f);
        for (int p = rs; p < re; p++) {
            float2 v = *(const float2*)&s_xbar[csr[p] * 8 + b2 * 2];
            a.x += v.x; a.y += v.y;
        }
        yh.x = fmaxf(yh.x + tau * (a.x - Bv.x), 0.f);
        yh.y = fmaxf(yh.y + tau * (a.y - Bv.y), 0.f);
        *(float2*)&s_yhead[i * 8 + b2 * 2] = yh;
        #pragma unroll
        for (int k = 0; k < 8; k++) {
            yt[k].x = fmaxf(yt[k].x - tau * xb[k].x, 0.f);
            yt[k].y = fmaxf(yt[k].y - tau * xb[k].y, 0.f);
        }
        __syncthreads();

        float2 d[8];
        float ssx = 0.f, ssy = 0.f;
        #pragma unroll
        for (int k = 0; k < 8; k++) {
            const int j = k * 64 + dl;
            float tvx = -yt[k].x, tvy = -yt[k].y;
            const int e = s_cp[j + 1];
            for (int p = s_cp[j]; p < e; p++) {
                float2 v = *(const float2*)&s_yhead[csc[p] * 8 + b2 * 2];
                tvx += v.x; tvy += v.y;
            }
            const float dx = x[k].x - tau * tvx + tau - z[k].x;
            const float dy = x[k].y - tau * tvy + tau - z[k].y;
            d[k] = make_float2(dx, dy);
            ssx += dx * dx;
            ssy += dy * dy;
        }
        ssx += __shfl_xor_sync(0xffffffffu, ssx, 4);
        ssy += __shfl_xor_sync(0xffffffffu, ssy, 4);
        ssx += __shfl_xor_sync(0xffffffffu, ssx, 8);
        ssy += __shfl_xor_sync(0xffffffffu, ssy, 8);
        ssx += __shfl_xor_sync(0xffffffffu, ssx, 16);
        ssy += __shfl_xor_sync(0xffffffffu, ssy, 16);
        if ((tid & 31) < 4) s_red[wid][b2] = make_float2(ssx, ssy);
        __syncthreads();

        float totx = 0.f, toty = 0.f;
        #pragma unroll
        for (int w = 0; w < 8; w++) {
            float2 r = s_red[w][b2];
            totx += r.x; toty += r.y;
        }
        const float scx = fmaxf(1.f - tau / fmaxf(sqrtf(totx), 1e-12f), 0.f);
        const float scy = fmaxf(1.f - tau / fmaxf(sqrtf(toty), 1e-12f), 0.f);
        #pragma unroll
        for (int k = 0; k < 8; k++) {
            const float xnx = z[k].x + scx * d[k].x;
            const float xny = z[k].y + scy * d[k].y;
            float2 xbn = make_float2(2.f * xnx - x[k].x, 2.f * xny - x[k].y);
            x[k]  = make_float2(xnx, xny);
            xb[k] = xbn;
            *(float2*)&s_xbar[(k * 64 + dl) * 8 + b2 * 2] = xbn;
        }
        __syncthreads();
    }

    #pragma unroll
    for (int k = 0; k < 8; k++) {
        const int j = k * 64 + dl;
        out[(size_t)r0 * NSTRUCT + j]       = x[k].x;
        out[(size_t)(r0 + 1) * NSTRUCT + j] = x[k].y;
    }
}

// ---------------- launch -------------------------------------------------
extern "C" void kernel_launch(void* const* d_in, const int* in_sizes, int n_in,
                              void* d_out, int out_size)
{
    const float* X  = (const float*)d_in[0];
    const float* W1 = (const float*)d_in[1];
    const float* b1 = (const float*)d_in[2];
    const float* W2 = (const float*)d_in[3];
    const float* b2 = (const float*)d_in[4];
    const float* W3 = (const float*)d_in[5];
    const float* b3 = (const float*)d_in[6];
    const float* S  = (const float*)d_in[7];
    float* out = (float*)d_out;

    prep_kernel<<<1, 512>>>(S);

    gemm1_kernel<<<dim3(NHID / 128,    NB_ROWS / 128), 256>>>(X, W1, b1);
    gemm2_kernel<<<dim3(NHID / 128,    NB_ROWS / 128), 256>>>(W2, b2);
    gemm3_kernel<<<dim3(NSTRUCT / 128, NB_ROWS / 64),  128>>>(W3, b3);

    pdhg_kernel<<<NB_ROWS / 8, 256>>>(X, out);
}

// round 13
// speedup vs baseline: 1.6523x; 1.0294x over previous
#include <cuda_runtime.h>
#include <cstdint>
#include <cstddef>

#define NB_ROWS 2048
#define NCOMBO  64
#define NSTRUCT 512
#define NHID    1024
#define NITER   60
#define PADNNZ  (NCOMBO * NSTRUCT + 1024)
#define SMNNZ   4096

// ---------------- device scratch ------------------------------------------
__device__ float g_C1[NB_ROWS * NHID];
__device__ float g_C2[NB_ROWS * NHID];
__device__ float g_Z [NB_ROWS * NSTRUCT];
__device__ int            g_row_ptr[NCOMBO + 1];             // even offsets
__device__ __align__(16) unsigned short g_csr_cols[PADNNZ];  // sentinel 512
__device__ int            g_col_ptr[NSTRUCT + 1];            // even offsets
__device__ __align__(16) unsigned short g_csc_rows[PADNNZ];  // sentinel 64
__device__ float g_tau;

// ---------------- helpers -------------------------------------------------
__device__ __forceinline__ void cp_async16(void* smem, const void* gmem) {
    unsigned s = (unsigned)__cvta_generic_to_shared(smem);
    asm volatile("cp.async.cg.shared.global [%0], [%1], 16;\n" :: "r"(s), "l"(gmem));
}
__device__ __forceinline__ void cp_commit() { asm volatile("cp.async.commit_group;\n"); }
template<int N_> __device__ __forceinline__ void cp_wait() {
    asm volatile("cp.async.wait_group %0;\n" :: "n"(N_));
}

// ---------------- prep: even-padded CSR/CSC + smem power iteration --------
__global__ void prep_kernel(const float* __restrict__ S)
{
    __shared__ unsigned char s8[NCOMBO * NSTRUCT];   // 32KB; reused for lists
    __shared__ float v[NSTRUCT + 1];                 // v[512] = 0 sentinel
    __shared__ float sv[NCOMBO + 1];                 // sv[64] = 0 sentinel
    __shared__ float red[16];
    __shared__ int   scnt[NCOMBO];
    __shared__ int   wtot[16];
    __shared__ int   srp[NCOMBO + 1];
    __shared__ int   scp[NSTRUCT + 1];

    const int t    = threadIdx.x;        // 512
    const int lane = t & 31;
    const int wid  = t >> 5;

    #pragma unroll 4
    for (int i = 0; i < NCOMBO; i++)
        s8[i * NSTRUCT + t] = (S[i * NSTRUCT + t] != 0.0f) ? 1 : 0;
    __syncthreads();

    // ---- CSR padded even, sentinel NSTRUCT ----
    if (t < NCOMBO) {
        int c = 0;
        for (int j = 0; j < NSTRUCT; j++) c += s8[t * NSTRUCT + j];
        scnt[t] = c;
    }
    __syncthreads();
    if (t == 0) {
        int acc = 0;
        for (int i = 0; i < NCOMBO; i++) {
            g_row_ptr[i] = acc; srp[i] = acc;
            acc += (scnt[i] + 1) & ~1;
        }
        g_row_ptr[NCOMBO] = acc; srp[NCOMBO] = acc;
    }
    __syncthreads();
    if (t < NCOMBO) {
        int p = srp[t];
        const int e = srp[t + 1];
        for (int j = 0; j < NSTRUCT; j++)
            if (s8[t * NSTRUCT + j]) g_csr_cols[p++] = (unsigned short)j;
        while (p < e) g_csr_cols[p++] = (unsigned short)NSTRUCT;
    }

    // ---- CSC padded even, sentinel NCOMBO; block scan ----
    int cc = 0;
    for (int i = 0; i < NCOMBO; i++) cc += s8[i * NSTRUCT + t];
    const int pc = (cc + 1) & ~1;
    int incl = pc;
    #pragma unroll
    for (int o = 1; o < 32; o <<= 1) {
        int nbr = __shfl_up_sync(0xffffffffu, incl, o);
        if (lane >= o) incl += nbr;
    }
    if (lane == 31) wtot[wid] = incl;
    __syncthreads();
    if (t < 16) {
        int xv = wtot[t];
        #pragma unroll
        for (int o = 1; o < 16; o <<= 1) {
            int nbr = __shfl_up_sync(0x0000ffffu, xv, o);
            if (t >= o) xv += nbr;
        }
        wtot[t] = xv;
    }
    __syncthreads();
    {
        int base = (wid > 0) ? wtot[wid - 1] : 0;
        int cend = base + incl;
        g_col_ptr[t + 1] = cend; scp[t + 1] = cend;
        if (t == 0) { g_col_ptr[0] = 0; scp[0] = 0; }
        int p = cend - pc;
        for (int i = 0; i < NCOMBO; i++)
            if (s8[i * NSTRUCT + t]) g_csc_rows[p++] = (unsigned short)i;
        while (p < cend) g_csc_rows[p++] = (unsigned short)NCOMBO;
    }
    __syncthreads();

    // ---- overlay lists into smem (s8 dead from here) ----
    unsigned short* sl_csr = (unsigned short*)s8;             // 8192 entries
    unsigned short* sl_csc = (unsigned short*)(s8 + 16384);   // 8192 entries
    const int nr = srp[NCOMBO];
    const int nc = scp[NSTRUCT];
    const bool ok = (nr <= 8192) && (nc <= 8192);
    if (ok) {
        for (int p = t; p < nr; p += 512) sl_csr[p] = g_csr_cols[p];
        for (int p = t; p < nc; p += 512) sl_csc[p] = g_csc_rows[p];
    }
    __syncthreads();
    const unsigned short* __restrict__ pcsr = ok ? sl_csr : g_csr_cols;
    const unsigned short* __restrict__ pcsc = ok ? sl_csc : g_csc_rows;

    // ---- power iteration on S^T S + I (all-smem, sentinels read 0) ----
    v[t] = 1.0f / sqrtf((float)NSTRUCT);
    if (t == 0) { v[NSTRUCT] = 0.f; sv[NCOMBO] = 0.f; }
    __syncthreads();
    for (int step = 0; step < 30; step++) {
        if (t < NCOMBO) {
            float a = 0.f;
            const int e = srp[t + 1];
            for (int p = srp[t]; p < e; p++) a += v[pcsr[p]];
            sv[t] = a;
        }
        __syncthreads();
        float w = v[t];
        {
            const int e = scp[t + 1];
            for (int p = scp[t]; p < e; p++) w += sv[pcsc[p]];
        }
        float sq = w * w;
        #pragma unroll
        for (int o = 16; o > 0; o >>= 1) sq += __shfl_xor_sync(0xffffffffu, sq, o);
        if (lane == 0) red[wid] = sq;
        __syncthreads();
        if (t == 0) {
            float s = 0.f;
            #pragma unroll
            for (int i = 0; i < 16; i++) s += red[i];
            red[0] = sqrtf(s);
        }
        __syncthreads();
        v[t] = w / red[0];
        __syncthreads();
    }
    if (t < NCOMBO) {
        float a = 0.f;
        const int e = srp[t + 1];
        for (int p = srp[t]; p < e; p++) a += v[pcsr[p]];
        sv[t] = a;
    }
    __syncthreads();
    {
        float w = v[t];
        const int e = scp[t + 1];
        for (int p = scp[t]; p < e; p++) w += sv[pcsc[p]];
        float sq = v[t] * w;
        #pragma unroll
        for (int o = 16; o > 0; o >>= 1) sq += __shfl_xor_sync(0xffffffffu, sq, o);
        if (lane == 0) red[wid] = sq;
        __syncthreads();
        if (t == 0) {
            float s = 0.f;
            #pragma unroll
            for (int i = 0; i < 16; i++) s += red[i];
            g_tau = 0.9f / sqrtf(s);
        }
    }
}

// ---------------- sgemm_v3: transposed-A smem (for 256-thread GEMMs) ------
template<int BM, int BN, int THREADS, int K, int N>
__device__ __forceinline__ void sgemm_v3(
    const float* __restrict__ A, const float* __restrict__ B,
    const float* __restrict__ bias, float* __restrict__ C)
{
    constexpr int KC = 16;
    constexpr int CA4 = BM * KC / 4 / THREADS;
    constexpr int CB  = KC * BN / 4;
    constexpr int NSTAGE = K / KC;
    __shared__ float As[2][KC][BM];
    __shared__ float Bs[2][KC][BN];

    const int tid = threadIdx.x;
    const int m0  = blockIdx.y * BM;
    const int n0  = blockIdx.x * BN;
    constexpr int TX = BN / 8;
    const int tx = tid % TX;
    const int ty = tid / TX;
    const int rowA = ty * 4;
    const int colA = tx * 4;

    float acc[8][8];
    #pragma unroll
    for (int i = 0; i < 8; i++)
        #pragma unroll
        for (int j = 0; j < 8; j++) acc[i][j] = 0.f;

    int am[CA4], akq[CA4];
    #pragma unroll
    for (int q = 0; q < CA4; q++) {
        const int c = tid + q * THREADS;
        am[q]  = c >> 2;
        akq[q] = (c & 3) * 4;
    }

    float4 areg[CA4];
    #pragma unroll
    for (int q = 0; q < CA4; q++)
        areg[q] = *(const float4*)(A + (size_t)(m0 + am[q]) * K + akq[q]);
    #pragma unroll
    for (int c = tid; c < CB; c += THREADS) {
        const int kr = c / (BN / 4);
        const int nq = (c % (BN / 4)) * 4;
        cp_async16(&Bs[0][kr][nq], B + (size_t)kr * N + n0 + nq);
    }
    cp_commit();

    for (int s = 0; s < NSTAGE; s++) {
        const int buf = s & 1;
        #pragma unroll
        for (int q = 0; q < CA4; q++) {
            As[buf][akq[q] + 0][am[q]] = areg[q].x;
            As[buf][akq[q] + 1][am[q]] = areg[q].y;
            As[buf][akq[q] + 2][am[q]] = areg[q].z;
            As[buf][akq[q] + 3][am[q]] = areg[q].w;
        }
        if (s + 1 < NSTAGE) {
            const int k0 = (s + 1) * KC;
            const int nb = (s + 1) & 1;
            #pragma unroll
            for (int c = tid; c < CB; c += THREADS) {
                const int kr = c / (BN / 4);
                const int nq = (c % (BN / 4)) * 4;
                cp_async16(&Bs[nb][kr][nq], B + (size_t)(k0 + kr) * N + n0 + nq);
            }
            cp_commit();
            cp_wait<1>();
        } else {
            cp_wait<0>();
        }
        __syncthreads();
        if (s + 1 < NSTAGE) {
            const int k0 = (s + 1) * KC;
            #pragma unroll
            for (int q = 0; q < CA4; q++)
                areg[q] = *(const float4*)(A + (size_t)(m0 + am[q]) * K + k0 + akq[q]);
        }
        #pragma unroll
        for (int kk = 0; kk < KC; kk++) {
            float fa[8], fb[8];
            *(float4*)&fa[0] = *(const float4*)&As[buf][kk][rowA];
            *(float4*)&fa[4] = *(const float4*)&As[buf][kk][rowA + BM / 2];
            *(float4*)&fb[0] = *(const float4*)&Bs[buf][kk][colA];
            *(float4*)&fb[4] = *(const float4*)&Bs[buf][kk][colA + BN / 2];
            #pragma unroll
            for (int i = 0; i < 8; i++)
                #pragma unroll
                for (int j = 0; j < 8; j++)
                    acc[i][j] = fmaf(fa[i], fb[j], acc[i][j]);
        }
        __syncthreads();
    }

    float4 bl = *(const float4*)(bias + n0 + colA);
    float4 bh = *(const float4*)(bias + n0 + colA + BN / 2);
    #pragma unroll
    for (int half = 0; half < 2; half++) {
        #pragma unroll
        for (int i = 0; i < 4; i++) {
            const int m  = m0 + rowA + half * (BM / 2) + i;
            const int ai = half * 4 + i;
            float4 o;
            o.x = fmaxf(acc[ai][0] + bl.x, 0.f);
            o.y = fmaxf(acc[ai][1] + bl.y, 0.f);
            o.z = fmaxf(acc[ai][2] + bl.z, 0.f);
            o.w = fmaxf(acc[ai][3] + bl.w, 0.f);
            *(float4*)(C + (size_t)m * N + n0 + colA) = o;
            float4 p;
            p.x = fmaxf(acc[ai][4] + bh.x, 0.f);
            p.y = fmaxf(acc[ai][5] + bh.y, 0.f);
            p.z = fmaxf(acc[ai][6] + bh.z, 0.f);
            p.w = fmaxf(acc[ai][7] + bh.w, 0.f);
            *(float4*)(C + (size_t)m * N + n0 + colA + BN / 2) = p;
        }
    }
}

// ---------------- sgemm_v2: scalar-A smem (for gemm3, 128 threads) --------
template<int BM, int BN, int THREADS, int K, int N>
__device__ __forceinline__ void sgemm_v2(
    const float* __restrict__ A, const float* __restrict__ B,
    const float* __restrict__ bias, float* __restrict__ C)
{
    constexpr int KC = 16;
    constexpr int CA = BM * KC / 4;
    constexpr int CB = KC * BN / 4;
    constexpr int NSTAGE = K / KC;
    __shared__ float As[2][BM][KC];
    __shared__ float Bs[2][KC][BN];

    const int tid = threadIdx.x;
    const int m0  = blockIdx.y * BM;
    const int n0  = blockIdx.x * BN;
    constexpr int TX = BN / 8;
    const int tx = tid % TX;
    const int ty = tid / TX;
    const int rowA = ty * 4;
    const int colA = tx * 4;

    float acc[8][8];
    #pragma unroll
    for (int i = 0; i < 8; i++)
        #pragma unroll
        for (int j = 0; j < 8; j++) acc[i][j] = 0.f;

    {
        #pragma unroll
        for (int c = tid; c < CA; c += THREADS) {
            int m  = c >> 2;
            int kq = (c & 3) * 4;
            cp_async16(&As[0][m][kq], A + (size_t)(m0 + m) * K + kq);
        }
        #pragma unroll
        for (int c = tid; c < CB; c += THREADS) {
            int kr = c / (BN / 4);
            int nq = (c % (BN / 4)) * 4;
            cp_async16(&Bs[0][kr][nq], B + (size_t)kr * N + n0 + nq);
        }
        cp_commit();
    }

    for (int s = 0; s < NSTAGE; s++) {
        if (s + 1 < NSTAGE) {
            const int k0 = (s + 1) * KC;
            const int nb = (s + 1) & 1;
            #pragma unroll
            for (int c = tid; c < CA; c += THREADS) {
                int m  = c >> 2;
                int kq = (c & 3) * 4;
                cp_async16(&As[nb][m][kq], A + (size_t)(m0 + m) * K + k0 + kq);
            }
            #pragma unroll
            for (int c = tid; c < CB; c += THREADS) {
                int kr = c / (BN / 4);
                int nq = (c % (BN / 4)) * 4;
                cp_async16(&Bs[nb][kr][nq], B + (size_t)(k0 + kr) * N + n0 + nq);
            }
            cp_commit();
            cp_wait<1>();
        } else {
            cp_wait<0>();
        }
        __syncthreads();
        const int buf = s & 1;
        #pragma unroll
        for (int kk = 0; kk < KC; kk++) {
            float fa[8], fb[8];
            #pragma unroll
            for (int i = 0; i < 4; i++) {
                fa[i]     = As[buf][rowA + i][kk];
                fa[4 + i] = As[buf][rowA + BM / 2 + i][kk];
            }
            *(float4*)&fb[0] = *(const float4*)&Bs[buf][kk][colA];
            *(float4*)&fb[4] = *(const float4*)&Bs[buf][kk][colA + BN / 2];
            #pragma unroll
            for (int i = 0; i < 8; i++)
                #pragma unroll
                for (int j = 0; j < 8; j++)
                    acc[i][j] = fmaf(fa[i], fb[j], acc[i][j]);
        }
        __syncthreads();
    }

    float4 bl = *(const float4*)(bias + n0 + colA);
    float4 bh = *(const float4*)(bias + n0 + colA + BN / 2);
    #pragma unroll
    for (int half = 0; half < 2; half++) {
        #pragma unroll
        for (int i = 0; i < 4; i++) {
            const int m  = m0 + rowA + half * (BM / 2) + i;
            const int ai = half * 4 + i;
            float4 o;
            o.x = fmaxf(acc[ai][0] + bl.x, 0.f);
            o.y = fmaxf(acc[ai][1] + bl.y, 0.f);
            o.z = fmaxf(acc[ai][2] + bl.z, 0.f);
            o.w = fmaxf(acc[ai][3] + bl.w, 0.f);
            *(float4*)(C + (size_t)m * N + n0 + colA) = o;
            float4 p;
            p.x = fmaxf(acc[ai][4] + bh.x, 0.f);
            p.y = fmaxf(acc[ai][5] + bh.y, 0.f);
            p.z = fmaxf(acc[ai][6] + bh.z, 0.f);
            p.w = fmaxf(acc[ai][7] + bh.w, 0.f);
            *(float4*)(C + (size_t)m * N + n0 + colA + BN / 2) = p;
        }
    }
}

__global__ __launch_bounds__(256, 2) void gemm1_kernel(
    const float* __restrict__ X, const float* __restrict__ W1, const float* __restrict__ b1)
{ sgemm_v3<128, 128, 256, NCOMBO, NHID>(X, W1, b1, g_C1); }

__global__ __launch_bounds__(256, 2) void gemm2_kernel(
    const float* __restrict__ W2, const float* __restrict__ b2)
{ sgemm_v3<128, 128, 256, NHID, NHID>(g_C1, W2, b2, g_C2); }

__global__ __launch_bounds__(128, 2) void gemm3_kernel(
    const float* __restrict__ W3, const float* __restrict__ b3)
{ sgemm_v2<64, 128, 128, NHID, NSTRUCT>(g_C2, W3, b3, g_Z); }

// ---------------- PDHG v7: R2 body + ushort2-packed indices ---------------
__global__ __launch_bounds__(256, 2) void pdhg_kernel(
    const float* __restrict__ Xg, float* __restrict__ out)
{
    __shared__ float s_xbar[(NSTRUCT + 1) * 8];   // col 512 = sentinel zeros
    __shared__ float s_yhead[(NCOMBO + 1) * 8];   // row 64  = sentinel zeros
    __shared__ ushort2 s_csr2[SMNNZ / 2];
    __shared__ ushort2 s_csc2[SMNNZ / 2];
    __shared__ int    s_rp[NCOMBO + 1];
    __shared__ int    s_cp[NSTRUCT + 1];
    __shared__ float2 s_red[8][4];

    const int tid = threadIdx.x;
    const int b2  = tid & 3;
    const int dl  = tid >> 2;
    const int wid = tid >> 5;
    const int r0  = blockIdx.x * 8 + b2 * 2;
    const int bo  = b2 * 2;

    for (int p = tid; p < NCOMBO + 1;  p += 256) s_rp[p] = g_row_ptr[p];
    for (int p = tid; p < NSTRUCT + 1; p += 256) s_cp[p] = g_col_ptr[p];
    for (int p = tid; p < (NSTRUCT + 1) * 8; p += 256) s_xbar[p] = 0.f;
    for (int p = tid; p < (NCOMBO + 1) * 8;  p += 256) s_yhead[p] = 0.f;
    __syncthreads();
    const int nnzr = s_rp[NCOMBO];
    const int nnzc = s_cp[NSTRUCT];
    const bool fits = (nnzr <= SMNNZ) && (nnzc <= SMNNZ);
    if (fits) {
        const ushort2* gr = (const ushort2*)g_csr_cols;
        const ushort2* gc = (const ushort2*)g_csc_rows;
        for (int p = tid; p < nnzr / 2; p += 256) s_csr2[p] = gr[p];
        for (int p = tid; p < nnzc / 2; p += 256) s_csc2[p] = gc[p];
    }
    const ushort2* __restrict__ csr2 = fits ? s_csr2 : (const ushort2*)g_csr_cols;
    const ushort2* __restrict__ csc2 = fits ? s_csc2 : (const ushort2*)g_csc_rows;
    const float tau = g_tau;

    float2 x[8], z[8], yt[8], xb[8];
    #pragma unroll
    for (int k = 0; k < 8; k++) {
        const int j = k * 64 + dl;
        z[k].x = g_Z[(size_t)r0 * NSTRUCT + j];
        z[k].y = g_Z[(size_t)(r0 + 1) * NSTRUCT + j];
        x[k]  = make_float2(0.f, 0.f);
        yt[k] = make_float2(0.f, 0.f);
        xb[k] = make_float2(0.f, 0.f);
    }
    const int i = dl;
    float2 Bv = make_float2(Xg[(size_t)r0 * NCOMBO + i],
                            Xg[(size_t)(r0 + 1) * NCOMBO + i]);
    float2 yh = make_float2(0.f, 0.f);
    const int rs2 = s_rp[i] >> 1, re2 = s_rp[i + 1] >> 1;
    __syncthreads();

    for (int it = 0; it < NITER; it++) {
        // ---- phase A: y-head (Kx over packed CSR) + y-tail ----
        float a0x = 0.f, a0y = 0.f, a1x = 0.f, a1y = 0.f;
        for (int p = rs2; p < re2; p++) {
            const ushort2 c = csr2[p];
            const float2 v0 = *(const float2*)&s_xbar[c.x * 8 + bo];
            const float2 v1 = *(const float2*)&s_xbar[c.y * 8 + bo];
            a0x += v0.x; a0y += v0.y;
            a1x += v1.x; a1y += v1.y;
        }
        yh.x = fmaxf(yh.x + tau * ((a0x + a1x) - Bv.x), 0.f);
        yh.y = fmaxf(yh.y + tau * ((a0y + a1y) - Bv.y), 0.f);
        *(float2*)&s_yhead[i * 8 + bo] = yh;
        #pragma unroll
        for (int k = 0; k < 8; k++) {
            yt[k].x = fmaxf(yt[k].x - tau * xb[k].x, 0.f);
            yt[k].y = fmaxf(yt[k].y - tau * xb[k].y, 0.f);
        }
        __syncthreads();

        // ---- phase B: KTy over packed CSC + prox residual ----
        float2 d[8];
        float ssx = 0.f, ssy = 0.f;
        #pragma unroll
        for (int k = 0; k < 8; k++) {
            const int j = k * 64 + dl;
            float t0x = -yt[k].x, t0y = -yt[k].y;
            float t1x = 0.f, t1y = 0.f;
            const int ps2 = s_cp[j] >> 1, pe2 = s_cp[j + 1] >> 1;
            for (int p = ps2; p < pe2; p++) {
                const ushort2 rr = csc2[p];
                const float2 va = *(const float2*)&s_yhead[rr.x * 8 + bo];
                const float2 vb = *(const float2*)&s_yhead[rr.y * 8 + bo];
                t0x += va.x; t0y += va.y;
                t1x += vb.x; t1y += vb.y;
            }
            const float dx = x[k].x - tau * (t0x + t1x) + tau - z[k].x;
            const float dy = x[k].y - tau * (t0y + t1y) + tau - z[k].y;
            d[k] = make_float2(dx, dy);
            ssx += dx * dx;
            ssy += dy * dy;
        }
        ssx += __shfl_xor_sync(0xffffffffu, ssx, 4);
        ssy += __shfl_xor_sync(0xffffffffu, ssy, 4);
        ssx += __shfl_xor_sync(0xffffffffu, ssx, 8);
        ssy += __shfl_xor_sync(0xffffffffu, ssy, 8);
        ssx += __shfl_xor_sync(0xffffffffu, ssx, 16);
        ssy += __shfl_xor_sync(0xffffffffu, ssy, 16);
        if ((tid & 31) < 4) s_red[wid][b2] = make_float2(ssx, ssy);
        __syncthreads();

        // ---- phase C: scale + x / xbar update ----
        float totx = 0.f, toty = 0.f;
        #pragma unroll
        for (int w = 0; w < 8; w++) {
            const float2 r = s_red[w][b2];
            totx += r.x; toty += r.y;
        }
        const float scx = fmaxf(1.f - tau / fmaxf(sqrtf(totx), 1e-12f), 0.f);
        const float scy = fmaxf(1.f - tau / fmaxf(sqrtf(toty), 1e-12f), 0.f);
        #pragma unroll
        for (int k = 0; k < 8; k++) {
            const float xnx = z[k].x + scx * d[k].x;
            const float xny = z[k].y + scy * d[k].y;
            const float2 xbn = make_float2(2.f * xnx - x[k].x, 2.f * xny - x[k].y);
            x[k]  = make_float2(xnx, xny);
            xb[k] = xbn;
            *(float2*)&s_xbar[(k * 64 + dl) * 8 + bo] = xbn;
        }
        __syncthreads();
    }

    #pragma unroll
    for (int k = 0; k < 8; k++) {
        const int j = k * 64 + dl;
        out[(size_t)r0 * NSTRUCT + j]       = x[k].x;
        out[(size_t)(r0 + 1) * NSTRUCT + j] = x[k].y;
    }
}

// ---------------- launch -------------------------------------------------
extern "C" void kernel_launch(void* const* d_in, const int* in_sizes, int n_in,
                              void* d_out, int out_size)
{
    const float* X  = (const float*)d_in[0];
    const float* W1 = (const float*)d_in[1];
    const float* b1 = (const float*)d_in[2];
    const float* W2 = (const float*)d_in[3];
    const float* b2 = (const float*)d_in[4];
    const float* W3 = (const float*)d_in[5];
    const float* b3 = (const float*)d_in[6];
    const float* S  = (const float*)d_in[7];
    float* out = (float*)d_out;

    prep_kernel<<<1, 512>>>(S);

    gemm1_kernel<<<dim3(NHID / 128,    NB_ROWS / 128), 256>>>(X, W1, b1);
    gemm2_kernel<<<dim3(NHID / 128,    NB_ROWS / 128), 256>>>(W2, b2);
    gemm3_kernel<<<dim3(NSTRUCT / 128, NB_ROWS / 64),  128>>>(W3, b3);

    pdhg_kernel<<<NB_ROWS / 8, 256>>>(X, out);
}

// round 14
// speedup vs baseline: 1.8311x; 1.1082x over previous
#include <cuda_runtime.h>
#include <cstdint>
#include <cstddef>

#define NB_ROWS 2048
#define NCOMBO  64
#define NSTRUCT 512
#define NHID    1024
#define NITER   60
#define PADNNZ  (NCOMBO * NSTRUCT + 1024)
#define SMNNZ   4096

// ---------------- device scratch ------------------------------------------
__device__ float g_C1[NB_ROWS * NHID];
__device__ float g_C2[NB_ROWS * NHID];
__device__ float g_Z [NB_ROWS * NSTRUCT];
__device__ int            g_row_ptr[NCOMBO + 1];             // even offsets
__device__ __align__(16) unsigned short g_csr_cols[PADNNZ];  // sentinel 512
__device__ int            g_col_ptr[NSTRUCT + 1];            // even offsets
__device__ __align__(16) unsigned short g_csc_rows[PADNNZ];  // sentinel 64
__device__ float g_tau;

// ---------------- helpers -------------------------------------------------
__device__ __forceinline__ void cp_async16(void* smem, const void* gmem) {
    unsigned s = (unsigned)__cvta_generic_to_shared(smem);
    asm volatile("cp.async.cg.shared.global [%0], [%1], 16;\n" :: "r"(s), "l"(gmem));
}
__device__ __forceinline__ void cp_commit() { asm volatile("cp.async.commit_group;\n"); }
template<int N_> __device__ __forceinline__ void cp_wait() {
    asm volatile("cp.async.wait_group %0;\n" :: "n"(N_));
}

// ---------------- shared pools for fused prep+gemm1 ----------------------
struct PrepSm {
    unsigned char s8[NCOMBO * NSTRUCT];   // 32KB; reused for list overlay
    float v[NSTRUCT + 1];
    float sv[NCOMBO + 1];
    float red[16];
    int   scnt[NCOMBO];
    int   wtot[16];
    int   srp[NCOMBO + 1];
    int   scp[NSTRUCT + 1];
};
struct GemmSm {
    float As[2][16][128];
    float Bs[2][16][128];
};

// ---------------- prep body (512 threads, 1 block) ------------------------
__device__ void prep_body(const float* __restrict__ S, char* pool)
{
    PrepSm& P = *(PrepSm*)pool;
    const int t    = threadIdx.x;        // 512
    const int lane = t & 31;
    const int wid  = t >> 5;

    #pragma unroll 4
    for (int i = 0; i < NCOMBO; i++)
        P.s8[i * NSTRUCT + t] = (S[i * NSTRUCT + t] != 0.0f) ? 1 : 0;
    __syncthreads();

    // ---- CSR padded even, sentinel NSTRUCT ----
    if (t < NCOMBO) {
        int c = 0;
        for (int j = 0; j < NSTRUCT; j++) c += P.s8[t * NSTRUCT + j];
        P.scnt[t] = c;
    }
    __syncthreads();
    if (t == 0) {
        int acc = 0;
        for (int i = 0; i < NCOMBO; i++) {
            g_row_ptr[i] = acc; P.srp[i] = acc;
            acc += (P.scnt[i] + 1) & ~1;
        }
        g_row_ptr[NCOMBO] = acc; P.srp[NCOMBO] = acc;
    }
    __syncthreads();
    if (t < NCOMBO) {
        int p = P.srp[t];
        const int e = P.srp[t + 1];
        for (int j = 0; j < NSTRUCT; j++)
            if (P.s8[t * NSTRUCT + j]) g_csr_cols[p++] = (unsigned short)j;
        while (p < e) g_csr_cols[p++] = (unsigned short)NSTRUCT;
    }

    // ---- CSC padded even, sentinel NCOMBO; block scan ----
    int cc = 0;
    for (int i = 0; i < NCOMBO; i++) cc += P.s8[i * NSTRUCT + t];
    const int pc = (cc + 1) & ~1;
    int incl = pc;
    #pragma unroll
    for (int o = 1; o < 32; o <<= 1) {
        int nbr = __shfl_up_sync(0xffffffffu, incl, o);
        if (lane >= o) incl += nbr;
    }
    if (lane == 31) P.wtot[wid] = incl;
    __syncthreads();
    if (t < 16) {
        int xv = P.wtot[t];
        #pragma unroll
        for (int o = 1; o < 16; o <<= 1) {
            int nbr = __shfl_up_sync(0x0000ffffu, xv, o);
            if (t >= o) xv += nbr;
        }
        P.wtot[t] = xv;
    }
    __syncthreads();
    {
        int base = (wid > 0) ? P.wtot[wid - 1] : 0;
        int cend = base + incl;
        g_col_ptr[t + 1] = cend; P.scp[t + 1] = cend;
        if (t == 0) { g_col_ptr[0] = 0; P.scp[0] = 0; }
        int p = cend - pc;
        for (int i = 0; i < NCOMBO; i++)
            if (P.s8[i * NSTRUCT + t]) g_csc_rows[p++] = (unsigned short)i;
        while (p < cend) g_csc_rows[p++] = (unsigned short)NCOMBO;
    }
    __syncthreads();

    // ---- overlay lists into s8 (dead from here) ----
    unsigned short* sl_csr = (unsigned short*)P.s8;             // 8192 entries
    unsigned short* sl_csc = (unsigned short*)(P.s8 + 16384);   // 8192 entries
    const int nr = P.srp[NCOMBO];
    const int nc = P.scp[NSTRUCT];
    const bool ok = (nr <= 8192) && (nc <= 8192);
    if (ok) {
        for (int p = t; p < nr; p += 512) sl_csr[p] = g_csr_cols[p];
        for (int p = t; p < nc; p += 512) sl_csc[p] = g_csc_rows[p];
    }
    __syncthreads();
    const unsigned short* __restrict__ pcsr = ok ? sl_csr : g_csr_cols;
    const unsigned short* __restrict__ pcsc = ok ? sl_csc : g_csc_rows;

    // ---- power iteration on S^T S + I (all-smem, sentinels read 0) ----
    P.v[t] = 1.0f / sqrtf((float)NSTRUCT);
    if (t == 0) { P.v[NSTRUCT] = 0.f; P.sv[NCOMBO] = 0.f; }
    __syncthreads();
    for (int step = 0; step < 30; step++) {
        if (t < NCOMBO) {
            float a = 0.f;
            const int e = P.srp[t + 1];
            for (int p = P.srp[t]; p < e; p++) a += P.v[pcsr[p]];
            P.sv[t] = a;
        }
        __syncthreads();
        float w = P.v[t];
        {
            const int e = P.scp[t + 1];
            for (int p = P.scp[t]; p < e; p++) w += P.sv[pcsc[p]];
        }
        float sq = w * w;
        #pragma unroll
        for (int o = 16; o > 0; o >>= 1) sq += __shfl_xor_sync(0xffffffffu, sq, o);
        if (lane == 0) P.red[wid] = sq;
        __syncthreads();
        if (t == 0) {
            float s = 0.f;
            #pragma unroll
            for (int i = 0; i < 16; i++) s += P.red[i];
            P.red[0] = sqrtf(s);
        }
        __syncthreads();
        P.v[t] = w / P.red[0];
        __syncthreads();
    }
    if (t < NCOMBO) {
        float a = 0.f;
        const int e = P.srp[t + 1];
        for (int p = P.srp[t]; p < e; p++) a += P.v[pcsr[p]];
        P.sv[t] = a;
    }
    __syncthreads();
    {
        float w = P.v[t];
        const int e = P.scp[t + 1];
        for (int p = P.scp[t]; p < e; p++) w += P.sv[pcsc[p]];
        float sq = P.v[t] * w;
        #pragma unroll
        for (int o = 16; o > 0; o >>= 1) sq += __shfl_xor_sync(0xffffffffu, sq, o);
        if (lane == 0) P.red[wid] = sq;
        __syncthreads();
        if (t == 0) {
            float s = 0.f;
            #pragma unroll
            for (int i = 0; i < 16; i++) s += P.red[i];
            g_tau = 0.9f / sqrtf(s);
        }
    }
}

// ---------------- sgemm_v3 body: transposed-A smem, explicit m0/n0 --------
template<int BM, int BN, int THREADS, int K, int N>
__device__ void sgemm_v3_body(
    const float* __restrict__ A, const float* __restrict__ B,
    const float* __restrict__ bias, float* __restrict__ C,
    int m0, int n0, char* pool)
{
    constexpr int KC = 16;
    constexpr int CA4 = BM * KC / 4 / THREADS;
    constexpr int CB  = KC * BN / 4;
    constexpr int NSTAGE = K / KC;
    GemmSm& G = *(GemmSm*)pool;

    const int tid = threadIdx.x;   // < THREADS guaranteed by caller
    constexpr int TX = BN / 8;
    const int tx = tid % TX;
    const int ty = tid / TX;
    const int rowA = ty * 4;
    const int colA = tx * 4;

    float acc[8][8];
    #pragma unroll
    for (int i = 0; i < 8; i++)
        #pragma unroll
        for (int j = 0; j < 8; j++) acc[i][j] = 0.f;

    int am[CA4], akq[CA4];
    #pragma unroll
    for (int q = 0; q < CA4; q++) {
        const int c = tid + q * THREADS;
        am[q]  = c >> 2;
        akq[q] = (c & 3) * 4;
    }

    float4 areg[CA4];
    #pragma unroll
    for (int q = 0; q < CA4; q++)
        areg[q] = *(const float4*)(A + (size_t)(m0 + am[q]) * K + akq[q]);
    #pragma unroll
    for (int c = tid; c < CB; c += THREADS) {
        const int kr = c / (BN / 4);
        const int nq = (c % (BN / 4)) * 4;
        cp_async16(&G.Bs[0][kr][nq], B + (size_t)kr * N + n0 + nq);
    }
    cp_commit();

    for (int s = 0; s < NSTAGE; s++) {
        const int buf = s & 1;
        #pragma unroll
        for (int q = 0; q < CA4; q++) {
            G.As[buf][akq[q] + 0][am[q]] = areg[q].x;
            G.As[buf][akq[q] + 1][am[q]] = areg[q].y;
            G.As[buf][akq[q] + 2][am[q]] = areg[q].z;
            G.As[buf][akq[q] + 3][am[q]] = areg[q].w;
        }
        if (s + 1 < NSTAGE) {
            const int k0 = (s + 1) * KC;
            const int nb = (s + 1) & 1;
            #pragma unroll
            for (int c = tid; c < CB; c += THREADS) {
                const int kr = c / (BN / 4);
                const int nq = (c % (BN / 4)) * 4;
                cp_async16(&G.Bs[nb][kr][nq], B + (size_t)(k0 + kr) * N + n0 + nq);
            }
            cp_commit();
            cp_wait<1>();
        } else {
            cp_wait<0>();
        }
        __syncthreads();
        if (s + 1 < NSTAGE) {
            const int k0 = (s + 1) * KC;
            #pragma unroll
            for (int q = 0; q < CA4; q++)
                areg[q] = *(const float4*)(A + (size_t)(m0 + am[q]) * K + k0 + akq[q]);
        }
        #pragma unroll
        for (int kk = 0; kk < KC; kk++) {
            float fa[8], fb[8];
            *(float4*)&fa[0] = *(const float4*)&G.As[buf][kk][rowA];
            *(float4*)&fa[4] = *(const float4*)&G.As[buf][kk][rowA + BM / 2];
            *(float4*)&fb[0] = *(const float4*)&G.Bs[buf][kk][colA];
            *(float4*)&fb[4] = *(const float4*)&G.Bs[buf][kk][colA + BN / 2];
            #pragma unroll
            for (int i = 0; i < 8; i++)
                #pragma unroll
                for (int j = 0; j < 8; j++)
                    acc[i][j] = fmaf(fa[i], fb[j], acc[i][j]);
        }
        __syncthreads();
    }

    float4 bl = *(const float4*)(bias + n0 + colA);
    float4 bh = *(const float4*)(bias + n0 + colA + BN / 2);
    #pragma unroll
    for (int half = 0; half < 2; half++) {
        #pragma unroll
        for (int i = 0; i < 4; i++) {
            const int m  = m0 + rowA + half * (BM / 2) + i;
            const int ai = half * 4 + i;
            float4 o;
            o.x = fmaxf(acc[ai][0] + bl.x, 0.f);
            o.y = fmaxf(acc[ai][1] + bl.y, 0.f);
            o.z = fmaxf(acc[ai][2] + bl.z, 0.f);
            o.w = fmaxf(acc[ai][3] + bl.w, 0.f);
            *(float4*)(C + (size_t)m * N + n0 + colA) = o;
            float4 p;
            p.x = fmaxf(acc[ai][4] + bh.x, 0.f);
            p.y = fmaxf(acc[ai][5] + bh.y, 0.f);
            p.z = fmaxf(acc[ai][6] + bh.z, 0.f);
            p.w = fmaxf(acc[ai][7] + bh.w, 0.f);
            *(float4*)(C + (size_t)m * N + n0 + colA + BN / 2) = p;
        }
    }
}

// ---------------- fused prep + gemm1 (grid 129 x 512 threads) -------------
__global__ __launch_bounds__(512, 1) void fused1_kernel(
    const float* __restrict__ X, const float* __restrict__ W1,
    const float* __restrict__ b1, const float* __restrict__ S)
{
    __shared__ __align__(16) char pool[sizeof(PrepSm) > sizeof(GemmSm)
                                       ? sizeof(PrepSm) : sizeof(GemmSm)];
    if (blockIdx.x == 128) {
        prep_body(S, pool);
        return;
    }
    if (threadIdx.x >= 256) return;    // exited threads don't block __syncthreads
    const int n0 = (blockIdx.x & 7) * 128;
    const int m0 = (blockIdx.x >> 3) * 128;
    sgemm_v3_body<128, 128, 256, NCOMBO, NHID>(X, W1, b1, g_C1, m0, n0, pool);
}

// ---------------- gemm2 (v3) / gemm3 (v2) ---------------------------------
__global__ __launch_bounds__(256, 2) void gemm2_kernel(
    const float* __restrict__ W2, const float* __restrict__ b2)
{
    __shared__ __align__(16) char pool[sizeof(GemmSm)];
    sgemm_v3_body<128, 128, 256, NHID, NHID>(g_C1, W2, b2, g_C2,
                                             blockIdx.y * 128, blockIdx.x * 128, pool);
}

template<int BM, int BN, int THREADS, int K, int N>
__device__ __forceinline__ void sgemm_v2(
    const float* __restrict__ A, const float* __restrict__ B,
    const float* __restrict__ bias, float* __restrict__ C)
{
    constexpr int KC = 16;
    constexpr int CA = BM * KC / 4;
    constexpr int CB = KC * BN / 4;
    constexpr int NSTAGE = K / KC;
    __shared__ float As[2][BM][KC];
    __shared__ float Bs[2][KC][BN];

    const int tid = threadIdx.x;
    const int m0  = blockIdx.y * BM;
    const int n0  = blockIdx.x * BN;
    constexpr int TX = BN / 8;
    const int tx = tid % TX;
    const int ty = tid / TX;
    const int rowA = ty * 4;
    const int colA = tx * 4;

    float acc[8][8];
    #pragma unroll
    for (int i = 0; i < 8; i++)
        #pragma unroll
        for (int j = 0; j < 8; j++) acc[i][j] = 0.f;

    {
        #pragma unroll
        for (int c = tid; c < CA; c += THREADS) {
            int m  = c >> 2;
            int kq = (c & 3) * 4;
            cp_async16(&As[0][m][kq], A + (size_t)(m0 + m) * K + kq);
        }
        #pragma unroll
        for (int c = tid; c < CB; c += THREADS) {
            int kr = c / (BN / 4);
            int nq = (c % (BN / 4)) * 4;
            cp_async16(&Bs[0][kr][nq], B + (size_t)kr * N + n0 + nq);
        }
        cp_commit();
    }

    for (int s = 0; s < NSTAGE; s++) {
        if (s + 1 < NSTAGE) {
            const int k0 = (s + 1) * KC;
            const int nb = (s + 1) & 1;
            #pragma unroll
            for (int c = tid; c < CA; c += THREADS) {
                int m  = c >> 2;
                int kq = (c & 3) * 4;
                cp_async16(&As[nb][m][kq], A + (size_t)(m0 + m) * K + k0 + kq);
            }
            #pragma unroll
            for (int c = tid; c < CB; c += THREADS) {
                int kr = c / (BN / 4);
                int nq = (c % (BN / 4)) * 4;
                cp_async16(&Bs[nb][kr][nq], B + (size_t)(k0 + kr) * N + n0 + nq);
            }
            cp_commit();
            cp_wait<1>();
        } else {
            cp_wait<0>();
        }
        __syncthreads();
        const int buf = s & 1;
        #pragma unroll
        for (int kk = 0; kk < KC; kk++) {
            float fa[8], fb[8];
            #pragma unroll
            for (int i = 0; i < 4; i++) {
                fa[i]     = As[buf][rowA + i][kk];
                fa[4 + i] = As[buf][rowA + BM / 2 + i][kk];
            }
            *(float4*)&fb[0] = *(const float4*)&Bs[buf][kk][colA];
            *(float4*)&fb[4] = *(const float4*)&Bs[buf][kk][colA + BN / 2];
            #pragma unroll
            for (int i = 0; i < 8; i++)
                #pragma unroll
                for (int j = 0; j < 8; j++)
                    acc[i][j] = fmaf(fa[i], fb[j], acc[i][j]);
        }
        __syncthreads();
    }

    float4 bl = *(const float4*)(bias + n0 + colA);
    float4 bh = *(const float4*)(bias + n0 + colA + BN / 2);
    #pragma unroll
    for (int half = 0; half < 2; half++) {
        #pragma unroll
        for (int i = 0; i < 4; i++) {
            const int m  = m0 + rowA + half * (BM / 2) + i;
            const int ai = half * 4 + i;
            float4 o;
            o.x = fmaxf(acc[ai][0] + bl.x, 0.f);
            o.y = fmaxf(acc[ai][1] + bl.y, 0.f);
            o.z = fmaxf(acc[ai][2] + bl.z, 0.f);
            o.w = fmaxf(acc[ai][3] + bl.w, 0.f);
            *(float4*)(C + (size_t)m * N + n0 + colA) = o;
            float4 p;
            p.x = fmaxf(acc[ai][4] + bh.x, 0.f);
            p.y = fmaxf(acc[ai][5] + bh.y, 0.f);
            p.z = fmaxf(acc[ai][6] + bh.z, 0.f);
            p.w = fmaxf(acc[ai][7] + bh.w, 0.f);
            *(float4*)(C + (size_t)m * N + n0 + colA + BN / 2) = p;
        }
    }
}

__global__ __launch_bounds__(128, 2) void gemm3_kernel(
    const float* __restrict__ W3, const float* __restrict__ b3)
{ sgemm_v2<64, 128, 128, NHID, NSTRUCT>(g_C2, W3, b3, g_Z); }

// ---------------- PDHG v8: batch tile 16, 512 threads, 128 CTAs -----------
// thread = (dl 0..63, b4 0..7): same per-thread work as v7, wider batch rows
// -> gathers are 4 random cols x 64B per warp (fewer conflict phases).
#define V8_XBAR  0
#define V8_YHEAD (V8_XBAR + (NSTRUCT + 1) * 16 * 4)
#define V8_CSR   (V8_YHEAD + (NCOMBO + 1) * 16 * 4)
#define V8_CSC   (V8_CSR + SMNNZ * 2)
#define V8_RP    (V8_CSC + SMNNZ * 2)
#define V8_CP    (V8_RP + (NCOMBO + 2) * 4)
#define V8_RED   ((V8_CP + (NSTRUCT + 2) * 4 + 15) & ~15)
#define V8_SMEM  (V8_RED + 16 * 8 * 8)

__global__ __launch_bounds__(512, 1) void pdhg_kernel(
    const float* __restrict__ Xg, float* __restrict__ out)
{
    extern __shared__ char smem[];
    float*   s_xbar  = (float*)(smem + V8_XBAR);
    float*   s_yhead = (float*)(smem + V8_YHEAD);
    ushort2* s_csr2  = (ushort2*)(smem + V8_CSR);
    ushort2* s_csc2  = (ushort2*)(smem + V8_CSC);
    int*     s_rp    = (int*)(smem + V8_RP);
    int*     s_cp    = (int*)(smem + V8_CP);
    float2*  s_red   = (float2*)(smem + V8_RED);   // [16 warps][8 b4]

    const int tid = threadIdx.x;
    const int b4  = tid & 7;        // batch pair 0..7
    const int dl  = tid >> 3;       // dim lane 0..63
    const int wid = tid >> 5;
    const int r0  = blockIdx.x * 16 + b4 * 2;
    const int bo  = b4 * 2;

    for (int p = tid; p < NCOMBO + 1;  p += 512) s_rp[p] = g_row_ptr[p];
    for (int p = tid; p < NSTRUCT + 1; p += 512) s_cp[p] = g_col_ptr[p];
    for (int p = tid; p < (NSTRUCT + 1) * 16; p += 512) s_xbar[p] = 0.f;
    for (int p = tid; p < (NCOMBO + 1) * 16;  p += 512) s_yhead[p] = 0.f;
    __syncthreads();
    const int nnzr = s_rp[NCOMBO];
    const int nnzc = s_cp[NSTRUCT];
    const bool fits = (nnzr <= SMNNZ) && (nnzc <= SMNNZ);
    if (fits) {
        const ushort2* gr = (const ushort2*)g_csr_cols;
        const ushort2* gc = (const ushort2*)g_csc_rows;
        for (int p = tid; p < nnzr / 2; p += 512) s_csr2[p] = gr[p];
        for (int p = tid; p < nnzc / 2; p += 512) s_csc2[p] = gc[p];
    }
    const ushort2* __restrict__ csr2 = fits ? s_csr2 : (const ushort2*)g_csr_cols;
    const ushort2* __restrict__ csc2 = fits ? s_csc2 : (const ushort2*)g_csc_rows;
    const float tau = g_tau;

    float2 x[8], z[8], yt[8], xb[8];
    #pragma unroll
    for (int k = 0; k < 8; k++) {
        const int j = k * 64 + dl;
        z[k].x = g_Z[(size_t)r0 * NSTRUCT + j];
        z[k].y = g_Z[(size_t)(r0 + 1) * NSTRUCT + j];
        x[k]  = make_float2(0.f, 0.f);
        yt[k] = make_float2(0.f, 0.f);
        xb[k] = make_float2(0.f, 0.f);
    }
    const int i = dl;
    float2 Bv = make_float2(Xg[(size_t)r0 * NCOMBO + i],
                            Xg[(size_t)(r0 + 1) * NCOMBO + i]);
    float2 yh = make_float2(0.f, 0.f);
    const int rs2 = s_rp[i] >> 1, re2 = s_rp[i + 1] >> 1;
    __syncthreads();

    for (int it = 0; it < NITER; it++) {
        // ---- phase A: y-head (Kx over packed CSR) + y-tail ----
        float a0x = 0.f, a0y = 0.f, a1x = 0.f, a1y = 0.f;
        for (int p = rs2; p < re2; p++) {
            const ushort2 c = csr2[p];
            const float2 v0 = *(const float2*)&s_xbar[c.x * 16 + bo];
            const float2 v1 = *(const float2*)&s_xbar[c.y * 16 + bo];
            a0x += v0.x; a0y += v0.y;
            a1x += v1.x; a1y += v1.y;
        }
        yh.x = fmaxf(yh.x + tau * ((a0x + a1x) - Bv.x), 0.f);
        yh.y = fmaxf(yh.y + tau * ((a0y + a1y) - Bv.y), 0.f);
        *(float2*)&s_yhead[i * 16 + bo] = yh;
        #pragma unroll
        for (int k = 0; k < 8; k++) {
            yt[k].x = fmaxf(yt[k].x - tau * xb[k].x, 0.f);
            yt[k].y = fmaxf(yt[k].y - tau * xb[k].y, 0.f);
        }
        __syncthreads();

        // ---- phase B: KTy over packed CSC + prox residual ----
        float2 d[8];
        float ssx = 0.f, ssy = 0.f;
        #pragma unroll
        for (int k = 0; k < 8; k++) {
            const int j = k * 64 + dl;
            float t0x = -yt[k].x, t0y = -yt[k].y;
            float t1x = 0.f, t1y = 0.f;
            const int ps2 = s_cp[j] >> 1, pe2 = s_cp[j + 1] >> 1;
            for (int p = ps2; p < pe2; p++) {
                const ushort2 rr = csc2[p];
                const float2 va = *(const float2*)&s_yhead[rr.x * 16 + bo];
                const float2 vb = *(const float2*)&s_yhead[rr.y * 16 + bo];
                t0x += va.x; t0y += va.y;
                t1x += vb.x; t1y += vb.y;
            }
            const float dx = x[k].x - tau * (t0x + t1x) + tau - z[k].x;
            const float dy = x[k].y - tau * (t0y + t1y) + tau - z[k].y;
            d[k] = make_float2(dx, dy);
            ssx += dx * dx;
            ssy += dy * dy;
        }
        // reduce over dl within warp: lane bits 3,4 vary dl
        ssx += __shfl_xor_sync(0xffffffffu, ssx, 8);
        ssy += __shfl_xor_sync(0xffffffffu, ssy, 8);
        ssx += __shfl_xor_sync(0xffffffffu, ssx, 16);
        ssy += __shfl_xor_sync(0xffffffffu, ssy, 16);
        if ((tid & 31) < 8) s_red[wid * 8 + b4] = make_float2(ssx, ssy);
        __syncthreads();

        // ---- phase C: scale + x / xbar update ----
        float totx = 0.f, toty = 0.f;
        #pragma unroll
        for (int w = 0; w < 16; w++) {
            const float2 r = s_red[w * 8 + b4];
            totx += r.x; toty += r.y;
        }
        const float scx = fmaxf(1.f - tau / fmaxf(sqrtf(totx), 1e-12f), 0.f);
        const float scy = fmaxf(1.f - tau / fmaxf(sqrtf(toty), 1e-12f), 0.f);
        #pragma unroll
        for (int k = 0; k < 8; k++) {
            const float xnx = z[k].x + scx * d[k].x;
            const float xny = z[k].y + scy * d[k].y;
            const float2 xbn = make_float2(2.f * xnx - x[k].x, 2.f * xny - x[k].y);
            x[k]  = make_float2(xnx, xny);
            xb[k] = xbn;
            *(float2*)&s_xbar[(k * 64 + dl) * 16 + bo] = xbn;
        }
        __syncthreads();
    }

    #pragma unroll
    for (int k = 0; k < 8; k++) {
        const int j = k * 64 + dl;
        out[(size_t)r0 * NSTRUCT + j]       = x[k].x;
        out[(size_t)(r0 + 1) * NSTRUCT + j] = x[k].y;
    }
}

// ---------------- launch -------------------------------------------------
extern "C" void kernel_launch(void* const* d_in, const int* in_sizes, int n_in,
                              void* d_out, int out_size)
{
    const float* X  = (const float*)d_in[0];
    const float* W1 = (const float*)d_in[1];
    const float* b1 = (const float*)d_in[2];
    const float* W2 = (const float*)d_in[3];
    const float* b2 = (const float*)d_in[4];
    const float* W3 = (const float*)d_in[5];
    const float* b3 = (const float*)d_in[6];
    const float* S  = (const float*)d_in[7];
    float* out = (float*)d_out;

    cudaFuncSetAttribute(pdhg_kernel,
                         cudaFuncAttributeMaxDynamicSharedMemorySize, V8_SMEM);

    fused1_kernel<<<129, 512>>>(X, W1, b1, S);
    gemm2_kernel<<<dim3(NHID / 128,    NB_ROWS / 128), 256>>>(W2, b2);
    gemm3_kernel<<<dim3(NSTRUCT / 128, NB_ROWS / 64),  128>>>(W3, b3);

    pdhg_kernel<<<NB_ROWS / 16, 512, V8_SMEM>>>(X, out);
}

// round 15
// speedup vs baseline: 1.9093x; 1.0427x over previous
#include <cuda_runtime.h>
#include <cstdint>
#include <cstddef>

#define NB_ROWS 2048
#define NCOMBO  64
#define NSTRUCT 512
#define NHID    1024
#define NITER   60
#define PADNNZ  (NCOMBO * NSTRUCT + 1024)
#define SMNNZ   4096

// ---------------- device scratch ------------------------------------------
__device__ float g_C1[NB_ROWS * NHID];
__device__ float g_C2[NB_ROWS * NHID];
__device__ float g_Z [NB_ROWS * NSTRUCT];
__device__ int            g_row_ptr[NCOMBO + 1];             // even offsets
__device__ __align__(16) unsigned short g_csr_cols[PADNNZ];  // sentinel 512
__device__ int            g_col_ptr[NSTRUCT + 1];            // even offsets
__device__ __align__(16) unsigned short g_csc_rows[PADNNZ];  // sentinel 64
__device__ float g_tau;

// ---------------- helpers -------------------------------------------------
__device__ __forceinline__ void cp_async16(void* smem, const void* gmem) {
    unsigned s = (unsigned)__cvta_generic_to_shared(smem);
    asm volatile("cp.async.cg.shared.global [%0], [%1], 16;\n" :: "r"(s), "l"(gmem));
}
__device__ __forceinline__ void cp_commit() { asm volatile("cp.async.commit_group;\n"); }
template<int N_> __device__ __forceinline__ void cp_wait() {
    asm volatile("cp.async.wait_group %0;\n" :: "n"(N_));
}

// ---------------- shared pools for fused prep+gemm1 ----------------------
struct PrepSm {
    unsigned char s8[NCOMBO * NSTRUCT];   // 32KB; reused for list overlay
    float v[NSTRUCT + 1];
    float sv[NCOMBO + 1];
    float red[16];
    int   scnt[NCOMBO];
    int   wtot[16];
    int   srp[NCOMBO + 1];
    int   scp[NSTRUCT + 1];
};
struct GemmSm {
    float As[2][16][128];
    float Bs[2][16][128];
};

// ---------------- prep body (512 threads, 1 block) ------------------------
__device__ void prep_body(const float* __restrict__ S, char* pool)
{
    PrepSm& P = *(PrepSm*)pool;
    const int t    = threadIdx.x;        // 512
    const int lane = t & 31;
    const int wid  = t >> 5;

    #pragma unroll 4
    for (int i = 0; i < NCOMBO; i++)
        P.s8[i * NSTRUCT + t] = (S[i * NSTRUCT + t] != 0.0f) ? 1 : 0;
    __syncthreads();

    if (t < NCOMBO) {
        int c = 0;
        for (int j = 0; j < NSTRUCT; j++) c += P.s8[t * NSTRUCT + j];
        P.scnt[t] = c;
    }
    __syncthreads();
    if (t == 0) {
        int acc = 0;
        for (int i = 0; i < NCOMBO; i++) {
            g_row_ptr[i] = acc; P.srp[i] = acc;
            acc += (P.scnt[i] + 1) & ~1;
        }
        g_row_ptr[NCOMBO] = acc; P.srp[NCOMBO] = acc;
    }
    __syncthreads();
    if (t < NCOMBO) {
        int p = P.srp[t];
        const int e = P.srp[t + 1];
        for (int j = 0; j < NSTRUCT; j++)
            if (P.s8[t * NSTRUCT + j]) g_csr_cols[p++] = (unsigned short)j;
        while (p < e) g_csr_cols[p++] = (unsigned short)NSTRUCT;
    }

    int cc = 0;
    for (int i = 0; i < NCOMBO; i++) cc += P.s8[i * NSTRUCT + t];
    const int pc = (cc + 1) & ~1;
    int incl = pc;
    #pragma unroll
    for (int o = 1; o < 32; o <<= 1) {
        int nbr = __shfl_up_sync(0xffffffffu, incl, o);
        if (lane >= o) incl += nbr;
    }
    if (lane == 31) P.wtot[wid] = incl;
    __syncthreads();
    if (t < 16) {
        int xv = P.wtot[t];
        #pragma unroll
        for (int o = 1; o < 16; o <<= 1) {
            int nbr = __shfl_up_sync(0x0000ffffu, xv, o);
            if (t >= o) xv += nbr;
        }
        P.wtot[t] = xv;
    }
    __syncthreads();
    {
        int base = (wid > 0) ? P.wtot[wid - 1] : 0;
        int cend = base + incl;
        g_col_ptr[t + 1] = cend; P.scp[t + 1] = cend;
        if (t == 0) { g_col_ptr[0] = 0; P.scp[0] = 0; }
        int p = cend - pc;
        for (int i = 0; i < NCOMBO; i++)
            if (P.s8[i * NSTRUCT + t]) g_csc_rows[p++] = (unsigned short)i;
        while (p < cend) g_csc_rows[p++] = (unsigned short)NCOMBO;
    }
    __syncthreads();

    unsigned short* sl_csr = (unsigned short*)P.s8;
    unsigned short* sl_csc = (unsigned short*)(P.s8 + 16384);
    const int nr = P.srp[NCOMBO];
    const int nc = P.scp[NSTRUCT];
    const bool ok = (nr <= 8192) && (nc <= 8192);
    if (ok) {
        for (int p = t; p < nr; p += 512) sl_csr[p] = g_csr_cols[p];
        for (int p = t; p < nc; p += 512) sl_csc[p] = g_csc_rows[p];
    }
    __syncthreads();
    const unsigned short* __restrict__ pcsr = ok ? sl_csr : g_csr_cols;
    const unsigned short* __restrict__ pcsc = ok ? sl_csc : g_csc_rows;

    P.v[t] = 1.0f / sqrtf((float)NSTRUCT);
    if (t == 0) { P.v[NSTRUCT] = 0.f; P.sv[NCOMBO] = 0.f; }
    __syncthreads();
    for (int step = 0; step < 30; step++) {
        if (t < NCOMBO) {
            float a = 0.f;
            const int e = P.srp[t + 1];
            for (int p = P.srp[t]; p < e; p++) a += P.v[pcsr[p]];
            P.sv[t] = a;
        }
        __syncthreads();
        float w = P.v[t];
        {
            const int e = P.scp[t + 1];
            for (int p = P.scp[t]; p < e; p++) w += P.sv[pcsc[p]];
        }
        float sq = w * w;
        #pragma unroll
        for (int o = 16; o > 0; o >>= 1) sq += __shfl_xor_sync(0xffffffffu, sq, o);
        if (lane == 0) P.red[wid] = sq;
        __syncthreads();
        if (t == 0) {
            float s = 0.f;
            #pragma unroll
            for (int i = 0; i < 16; i++) s += P.red[i];
            P.red[0] = sqrtf(s);
        }
        __syncthreads();
        P.v[t] = w / P.red[0];
        __syncthreads();
    }
    if (t < NCOMBO) {
        float a = 0.f;
        const int e = P.srp[t + 1];
        for (int p = P.srp[t]; p < e; p++) a += P.v[pcsr[p]];
        P.sv[t] = a;
    }
    __syncthreads();
    {
        float w = P.v[t];
        const int e = P.scp[t + 1];
        for (int p = P.scp[t]; p < e; p++) w += P.sv[pcsc[p]];
        float sq = P.v[t] * w;
        #pragma unroll
        for (int o = 16; o > 0; o >>= 1) sq += __shfl_xor_sync(0xffffffffu, sq, o);
        if (lane == 0) P.red[wid] = sq;
        __syncthreads();
        if (t == 0) {
            float s = 0.f;
            #pragma unroll
            for (int i = 0; i < 16; i++) s += P.red[i];
            g_tau = 0.9f / sqrtf(s);
        }
    }
}

// ---------------- sgemm_v3 body: transposed-A smem, explicit m0/n0 --------
template<int BM, int BN, int THREADS, int K, int N>
__device__ void sgemm_v3_body(
    const float* __restrict__ A, const float* __restrict__ B,
    const float* __restrict__ bias, float* __restrict__ C,
    int m0, int n0, char* pool)
{
    constexpr int KC = 16;
    constexpr int CA4 = BM * KC / 4 / THREADS;
    constexpr int CB  = KC * BN / 4;
    constexpr int NSTAGE = K / KC;
    GemmSm& G = *(GemmSm*)pool;

    const int tid = threadIdx.x;
    constexpr int TX = BN / 8;
    const int tx = tid % TX;
    const int ty = tid / TX;
    const int rowA = ty * 4;
    const int colA = tx * 4;

    float acc[8][8];
    #pragma unroll
    for (int i = 0; i < 8; i++)
        #pragma unroll
        for (int j = 0; j < 8; j++) acc[i][j] = 0.f;

    int am[CA4], akq[CA4];
    #pragma unroll
    for (int q = 0; q < CA4; q++) {
        const int c = tid + q * THREADS;
        am[q]  = c >> 2;
        akq[q] = (c & 3) * 4;
    }

    float4 areg[CA4];
    #pragma unroll
    for (int q = 0; q < CA4; q++)
        areg[q] = *(const float4*)(A + (size_t)(m0 + am[q]) * K + akq[q]);
    #pragma unroll
    for (int c = tid; c < CB; c += THREADS) {
        const int kr = c / (BN / 4);
        const int nq = (c % (BN / 4)) * 4;
        cp_async16(&G.Bs[0][kr][nq], B + (size_t)kr * N + n0 + nq);
    }
    cp_commit();

    for (int s = 0; s < NSTAGE; s++) {
        const int buf = s & 1;
        #pragma unroll
        for (int q = 0; q < CA4; q++) {
            G.As[buf][akq[q] + 0][am[q]] = areg[q].x;
            G.As[buf][akq[q] + 1][am[q]] = areg[q].y;
            G.As[buf][akq[q] + 2][am[q]] = areg[q].z;
            G.As[buf][akq[q] + 3][am[q]] = areg[q].w;
        }
        if (s + 1 < NSTAGE) {
            const int k0 = (s + 1) * KC;
            const int nb = (s + 1) & 1;
            #pragma unroll
            for (int c = tid; c < CB; c += THREADS) {
                const int kr = c / (BN / 4);
                const int nq = (c % (BN / 4)) * 4;
                cp_async16(&G.Bs[nb][kr][nq], B + (size_t)(k0 + kr) * N + n0 + nq);
            }
            cp_commit();
            cp_wait<1>();
        } else {
            cp_wait<0>();
        }
        __syncthreads();
        if (s + 1 < NSTAGE) {
            const int k0 = (s + 1) * KC;
            #pragma unroll
            for (int q = 0; q < CA4; q++)
                areg[q] = *(const float4*)(A + (size_t)(m0 + am[q]) * K + k0 + akq[q]);
        }
        #pragma unroll
        for (int kk = 0; kk < KC; kk++) {
            float fa[8], fb[8];
            *(float4*)&fa[0] = *(const float4*)&G.As[buf][kk][rowA];
            *(float4*)&fa[4] = *(const float4*)&G.As[buf][kk][rowA + BM / 2];
            *(float4*)&fb[0] = *(const float4*)&G.Bs[buf][kk][colA];
            *(float4*)&fb[4] = *(const float4*)&G.Bs[buf][kk][colA + BN / 2];
            #pragma unroll
            for (int i = 0; i < 8; i++)
                #pragma unroll
                for (int j = 0; j < 8; j++)
                    acc[i][j] = fmaf(fa[i], fb[j], acc[i][j]);
        }
        __syncthreads();
    }

    float4 bl = *(const float4*)(bias + n0 + colA);
    float4 bh = *(const float4*)(bias + n0 + colA + BN / 2);
    #pragma unroll
    for (int half = 0; half < 2; half++) {
        #pragma unroll
        for (int i = 0; i < 4; i++) {
            const int m  = m0 + rowA + half * (BM / 2) + i;
            const int ai = half * 4 + i;
            float4 o;
            o.x = fmaxf(acc[ai][0] + bl.x, 0.f);
            o.y = fmaxf(acc[ai][1] + bl.y, 0.f);
            o.z = fmaxf(acc[ai][2] + bl.z, 0.f);
            o.w = fmaxf(acc[ai][3] + bl.w, 0.f);
            *(float4*)(C + (size_t)m * N + n0 + colA) = o;
            float4 p;
            p.x = fmaxf(acc[ai][4] + bh.x, 0.f);
            p.y = fmaxf(acc[ai][5] + bh.y, 0.f);
            p.z = fmaxf(acc[ai][6] + bh.z, 0.f);
            p.w = fmaxf(acc[ai][7] + bh.w, 0.f);
            *(float4*)(C + (size_t)m * N + n0 + colA + BN / 2) = p;
        }
    }
}

// ---------------- fused prep + gemm1 (grid 129 x 512 threads) -------------
__global__ __launch_bounds__(512, 1) void fused1_kernel(
    const float* __restrict__ X, const float* __restrict__ W1,
    const float* __restrict__ b1, const float* __restrict__ S)
{
    __shared__ __align__(16) char pool[sizeof(PrepSm) > sizeof(GemmSm)
                                       ? sizeof(PrepSm) : sizeof(GemmSm)];
    if (blockIdx.x == 128) {
        prep_body(S, pool);
        return;
    }
    if (threadIdx.x >= 256) return;
    const int n0 = (blockIdx.x & 7) * 128;
    const int m0 = (blockIdx.x >> 3) * 128;
    sgemm_v3_body<128, 128, 256, NCOMBO, NHID>(X, W1, b1, g_C1, m0, n0, pool);
}

__global__ __launch_bounds__(256, 2) void gemm2_kernel(
    const float* __restrict__ W2, const float* __restrict__ b2)
{
    __shared__ __align__(16) char pool[sizeof(GemmSm)];
    sgemm_v3_body<128, 128, 256, NHID, NHID>(g_C1, W2, b2, g_C2,
                                             blockIdx.y * 128, blockIdx.x * 128, pool);
}

// ---------------- gemm3: v3h (BM=64, 256 threads, acc 4x8, transposed A) --
__global__ __launch_bounds__(256, 2) void gemm3_kernel(
    const float* __restrict__ W3, const float* __restrict__ b3)
{
    constexpr int BM = 64, BN = 128, TH = 256, KC = 16, K = NHID, N = NSTRUCT;
    constexpr int CB = KC * BN / 4;
    constexpr int NSTAGE = K / KC;
    __shared__ float As[2][KC][BM];   // 8KB
    __shared__ float Bs[2][KC][BN];   // 16KB
    const float* A = g_C2;
    const int tid = threadIdx.x;
    const int m0 = blockIdx.y * BM, n0 = blockIdx.x * BN;
    const int tx = tid & 15;          // 0..15
    const int ty = tid >> 4;          // 0..15
    const int rowA = ty * 2;
    const int colA = tx * 4;

    float acc[4][8];
    #pragma unroll
    for (int i = 0; i < 4; i++)
        #pragma unroll
        for (int j = 0; j < 8; j++) acc[i][j] = 0.f;

    const int am  = tid >> 2;
    const int akq = (tid & 3) * 4;

    float4 areg = *(const float4*)(A + (size_t)(m0 + am) * K + akq);
    #pragma unroll
    for (int c = tid; c < CB; c += TH) {
        const int kr = c / 32;
        const int nq = (c % 32) * 4;
        cp_async16(&Bs[0][kr][nq], W3 + (size_t)kr * N + n0 + nq);
    }
    cp_commit();

    for (int s = 0; s < NSTAGE; s++) {
        const int buf = s & 1;
        As[buf][akq + 0][am] = areg.x;
        As[buf][akq + 1][am] = areg.y;
        As[buf][akq + 2][am] = areg.z;
        As[buf][akq + 3][am] = areg.w;
        if (s + 1 < NSTAGE) {
            const int k0 = (s + 1) * KC;
            const int nb = (s + 1) & 1;
            #pragma unroll
            for (int c = tid; c < CB; c += TH) {
                const int kr = c / 32;
                const int nq = (c % 32) * 4;
                cp_async16(&Bs[nb][kr][nq], W3 + (size_t)(k0 + kr) * N + n0 + nq);
            }
            cp_commit();
            cp_wait<1>();
        } else {
            cp_wait<0>();
        }
        __syncthreads();
        if (s + 1 < NSTAGE) {
            const int k0 = (s + 1) * KC;
            areg = *(const float4*)(A + (size_t)(m0 + am) * K + k0 + akq);
        }
        #pragma unroll
        for (int kk = 0; kk < KC; kk++) {
            float fa[4], fb[8];
            *(float2*)&fa[0] = *(const float2*)&As[buf][kk][rowA];
            *(float2*)&fa[2] = *(const float2*)&As[buf][kk][rowA + 32];
            *(float4*)&fb[0] = *(const float4*)&Bs[buf][kk][colA];
            *(float4*)&fb[4] = *(const float4*)&Bs[buf][kk][colA + 64];
            #pragma unroll
            for (int i = 0; i < 4; i++)
                #pragma unroll
                for (int j = 0; j < 8; j++)
                    acc[i][j] = fmaf(fa[i], fb[j], acc[i][j]);
        }
        __syncthreads();
    }

    float4 bl = *(const float4*)(b3 + n0 + colA);
    float4 bh = *(const float4*)(b3 + n0 + colA + 64);
    #pragma unroll
    for (int half = 0; half < 2; half++) {
        #pragma unroll
        for (int i = 0; i < 2; i++) {
            const int m  = m0 + half * 32 + rowA + i;
            const int ai = half * 2 + i;
            float4 o;
            o.x = fmaxf(acc[ai][0] + bl.x, 0.f);
            o.y = fmaxf(acc[ai][1] + bl.y, 0.f);
            o.z = fmaxf(acc[ai][2] + bl.z, 0.f);
            o.w = fmaxf(acc[ai][3] + bl.w, 0.f);
            *(float4*)(g_Z + (size_t)m * N + n0 + colA) = o;
            float4 p;
            p.x = fmaxf(acc[ai][4] + bh.x, 0.f);
            p.y = fmaxf(acc[ai][5] + bh.y, 0.f);
            p.z = fmaxf(acc[ai][6] + bh.z, 0.f);
            p.w = fmaxf(acc[ai][7] + bh.w, 0.f);
            *(float4*)(g_Z + (size_t)m * N + n0 + colA + 64) = p;
        }
    }
}

// ---------------- PDHG v9: v8 + staged scale reduction --------------------
#define V8_XBAR  0
#define V8_YHEAD (V8_XBAR + (NSTRUCT + 1) * 16 * 4)
#define V8_CSR   (V8_YHEAD + (NCOMBO + 1) * 16 * 4)
#define V8_CSC   (V8_CSR + SMNNZ * 2)
#define V8_RP    (V8_CSC + SMNNZ * 2)
#define V8_CP    (V8_RP + (NCOMBO + 2) * 4)
#define V8_RED   ((V8_CP + (NSTRUCT + 2) * 4 + 15) & ~15)
#define V8_SCALE (V8_RED + 16 * 8 * 8)
#define V8_SMEM  (V8_SCALE + 8 * 8)

__global__ __launch_bounds__(512, 1) void pdhg_kernel(
    const float* __restrict__ Xg, float* __restrict__ out)
{
    extern __shared__ char smem[];
    float*   s_xbar  = (float*)(smem + V8_XBAR);
    float*   s_yhead = (float*)(smem + V8_YHEAD);
    ushort2* s_csr2  = (ushort2*)(smem + V8_CSR);
    ushort2* s_csc2  = (ushort2*)(smem + V8_CSC);
    int*     s_rp    = (int*)(smem + V8_RP);
    int*     s_cp    = (int*)(smem + V8_CP);
    float2*  s_red   = (float2*)(smem + V8_RED);     // [16 warps][8 b4]
    float2*  s_scale = (float2*)(smem + V8_SCALE);   // [8 b4]

    const int tid = threadIdx.x;
    const int b4  = tid & 7;
    const int dl  = tid >> 3;
    const int wid = tid >> 5;
    const int r0  = blockIdx.x * 16 + b4 * 2;
    const int bo  = b4 * 2;

    for (int p = tid; p < NCOMBO + 1;  p += 512) s_rp[p] = g_row_ptr[p];
    for (int p = tid; p < NSTRUCT + 1; p += 512) s_cp[p] = g_col_ptr[p];
    for (int p = tid; p < (NSTRUCT + 1) * 16; p += 512) s_xbar[p] = 0.f;
    for (int p = tid; p < (NCOMBO + 1) * 16;  p += 512) s_yhead[p] = 0.f;
    __syncthreads();
    const int nnzr = s_rp[NCOMBO];
    const int nnzc = s_cp[NSTRUCT];
    const bool fits = (nnzr <= SMNNZ) && (nnzc <= SMNNZ);
    if (fits) {
        const ushort2* gr = (const ushort2*)g_csr_cols;
        const ushort2* gc = (const ushort2*)g_csc_rows;
        for (int p = tid; p < nnzr / 2; p += 512) s_csr2[p] = gr[p];
        for (int p = tid; p < nnzc / 2; p += 512) s_csc2[p] = gc[p];
    }
    const ushort2* __restrict__ csr2 = fits ? s_csr2 : (const ushort2*)g_csr_cols;
    const ushort2* __restrict__ csc2 = fits ? s_csc2 : (const ushort2*)g_csc_rows;
    const float tau = g_tau;

    float2 x[8], z[8], yt[8], xb[8];
    #pragma unroll
    for (int k = 0; k < 8; k++) {
        const int j = k * 64 + dl;
        z[k].x = g_Z[(size_t)r0 * NSTRUCT + j];
        z[k].y = g_Z[(size_t)(r0 + 1) * NSTRUCT + j];
        x[k]  = make_float2(0.f, 0.f);
        yt[k] = make_float2(0.f, 0.f);
        xb[k] = make_float2(0.f, 0.f);
    }
    const int i = dl;
    float2 Bv = make_float2(Xg[(size_t)r0 * NCOMBO + i],
                            Xg[(size_t)(r0 + 1) * NCOMBO + i]);
    float2 yh = make_float2(0.f, 0.f);
    const int rs2 = s_rp[i] >> 1, re2 = s_rp[i + 1] >> 1;
    __syncthreads();

    for (int it = 0; it < NITER; it++) {
        // ---- phase A: y-head (Kx over packed CSR) + y-tail ----
        float a0x = 0.f, a0y = 0.f, a1x = 0.f, a1y = 0.f;
        #pragma unroll 2
        for (int p = rs2; p < re2; p++) {
            const ushort2 c = csr2[p];
            const float2 v0 = *(const float2*)&s_xbar[c.x * 16 + bo];
            const float2 v1 = *(const float2*)&s_xbar[c.y * 16 + bo];
            a0x += v0.x; a0y += v0.y;
            a1x += v1.x; a1y += v1.y;
        }
        yh.x = fmaxf(yh.x + tau * ((a0x + a1x) - Bv.x), 0.f);
        yh.y = fmaxf(yh.y + tau * ((a0y + a1y) - Bv.y), 0.f);
        *(float2*)&s_yhead[i * 16 + bo] = yh;
        #pragma unroll
        for (int k = 0; k < 8; k++) {
            yt[k].x = fmaxf(yt[k].x - tau * xb[k].x, 0.f);
            yt[k].y = fmaxf(yt[k].y - tau * xb[k].y, 0.f);
        }
        __syncthreads();

        // ---- phase B: KTy over packed CSC + prox residual ----
        float2 d[8];
        float ssx = 0.f, ssy = 0.f;
        #pragma unroll
        for (int k = 0; k < 8; k++) {
            const int j = k * 64 + dl;
            float t0x = -yt[k].x, t0y = -yt[k].y;
            float t1x = 0.f, t1y = 0.f;
            const int ps2 = s_cp[j] >> 1, pe2 = s_cp[j + 1] >> 1;
            for (int p = ps2; p < pe2; p++) {
                const ushort2 rr = csc2[p];
                const float2 va = *(const float2*)&s_yhead[rr.x * 16 + bo];
                const float2 vb = *(const float2*)&s_yhead[rr.y * 16 + bo];
                t0x += va.x; t0y += va.y;
                t1x += vb.x; t1y += vb.y;
            }
            const float dx = x[k].x - tau * (t0x + t1x) + tau - z[k].x;
            const float dy = x[k].y - tau * (t0y + t1y) + tau - z[k].y;
            d[k] = make_float2(dx, dy);
            ssx += dx * dx;
            ssy += dy * dy;
        }
        ssx += __shfl_xor_sync(0xffffffffu, ssx, 8);
        ssy += __shfl_xor_sync(0xffffffffu, ssy, 8);
        ssx += __shfl_xor_sync(0xffffffffu, ssx, 16);
        ssy += __shfl_xor_sync(0xffffffffu, ssy, 16);
        if ((tid & 31) < 8) s_red[wid * 8 + b4] = make_float2(ssx, ssy);
        __syncthreads();

        // ---- phase C1: 8 threads compute the 8 scales ----
        if (tid < 8) {
            float totx = 0.f, toty = 0.f;
            #pragma unroll
            for (int w = 0; w < 16; w++) {
                const float2 r = s_red[w * 8 + tid];
                totx += r.x; toty += r.y;
            }
            float2 sc;
            sc.x = fmaxf(1.f - tau / fmaxf(sqrtf(totx), 1e-12f), 0.f);
            sc.y = fmaxf(1.f - tau / fmaxf(sqrtf(toty), 1e-12f), 0.f);
            s_scale[tid] = sc;
        }
        __syncthreads();

        // ---- phase C2: x / xbar update ----
        const float2 sc = s_scale[b4];
        #pragma unroll
        for (int k = 0; k < 8; k++) {
            const float xnx = z[k].x + sc.x * d[k].x;
            const float xny = z[k].y + sc.y * d[k].y;
            const float2 xbn = make_float2(2.f * xnx - x[k].x, 2.f * xny - x[k].y);
            x[k]  = make_float2(xnx, xny);
            xb[k] = xbn;
            *(float2*)&s_xbar[(k * 64 + dl) * 16 + bo] = xbn;
        }
        __syncthreads();
    }

    #pragma unroll
    for (int k = 0; k < 8; k++) {
        const int j = k * 64 + dl;
        out[(size_t)r0 * NSTRUCT + j]       = x[k].x;
        out[(size_t)(r0 + 1) * NSTRUCT + j] = x[k].y;
    }
}

// ---------------- launch -------------------------------------------------
extern "C" void kernel_launch(void* const* d_in, const int* in_sizes, int n_in,
                              void* d_out, int out_size)
{
    const float* X  = (const float*)d_in[0];
    const float* W1 = (const float*)d_in[1];
    const float* b1 = (const float*)d_in[2];
    const float* W2 = (const float*)d_in[3];
    const float* b2 = (const float*)d_in[4];
    const float* W3 = (const float*)d_in[5];
    const float* b3 = (const float*)d_in[6];
    const float* S  = (const float*)d_in[7];
    float* out = (float*)d_out;

    cudaFuncSetAttribute(pdhg_kernel,
                         cudaFuncAttributeMaxDynamicSharedMemorySize, V8_SMEM);

    fused1_kernel<<<129, 512>>>(X, W1, b1, S);
    gemm2_kernel<<<dim3(NHID / 128,    NB_ROWS / 128), 256>>>(W2, b2);
    gemm3_kernel<<<dim3(NSTRUCT / 128, NB_ROWS / 64),  256>>>(W3, b3);

    pdhg_kernel<<<NB_ROWS / 16, 512, V8_SMEM>>>(X, out);
}

// round 16
// speedup vs baseline: 1.9519x; 1.0223x over previous
#include <cuda_runtime.h>
#include <cstdint>
#include <cstddef>

#define NB_ROWS 2048
#define NCOMBO  64
#define NSTRUCT 512
#define NHID    1024
#define NITER   60
#define PADNNZ  (NCOMBO * NSTRUCT + 1024)
#define SMNNZ   4096

typedef unsigned long long u64;

// ---------------- device scratch ------------------------------------------
__device__ float g_C1[NB_ROWS * NHID];
__device__ float g_C2[NB_ROWS * NHID];
__device__ float g_Z [NB_ROWS * NSTRUCT];
__device__ int            g_row_ptr[NCOMBO + 1];             // even offsets
__device__ __align__(16) unsigned short g_csr_cols[PADNNZ];  // sentinel 512
__device__ int            g_col_ptr[NSTRUCT + 1];            // even offsets
__device__ __align__(16) unsigned short g_csc_rows[PADNNZ];  // sentinel 64
__device__ float g_tau;

// ---------------- helpers -------------------------------------------------
__device__ __forceinline__ void cp_async16(void* smem, const void* gmem) {
    unsigned s = (unsigned)__cvta_generic_to_shared(smem);
    asm volatile("cp.async.cg.shared.global [%0], [%1], 16;\n" :: "r"(s), "l"(gmem));
}
__device__ __forceinline__ void cp_commit() { asm volatile("cp.async.commit_group;\n"); }
template<int N_> __device__ __forceinline__ void cp_wait() {
    asm volatile("cp.async.wait_group %0;\n" :: "n"(N_));
}
__device__ __forceinline__ u64 packdup(float a) {
    u64 r;
    asm("mov.b64 %0, {%1, %1};" : "=l"(r) : "r"(__float_as_uint(a)));
    return r;
}
__device__ __forceinline__ void fma2(u64& d, u64 a, u64 b) {
    asm("fma.rn.f32x2 %0, %1, %2, %0;" : "+l"(d) : "l"(a), "l"(b));
}
__device__ __forceinline__ float2 unpack2(u64 v) {
    unsigned lo, hi;
    asm("mov.b64 {%0, %1}, %2;" : "=r"(lo), "=r"(hi) : "l"(v));
    return make_float2(__uint_as_float(lo), __uint_as_float(hi));
}

// ---------------- shared pools for fused prep+gemm1 ----------------------
struct PrepSm {
    unsigned char s8[NCOMBO * NSTRUCT];
    float v[NSTRUCT + 1];
    float sv[NCOMBO + 1];
    float red[16];
    int   scnt[NCOMBO];
    int   wtot[16];
    int   srp[NCOMBO + 1];
    int   scp[NSTRUCT + 1];
};
struct GemmSm {
    float As[2][16][128];
    float Bs[2][16][128];
};

// ---------------- prep body (512 threads, 1 block) ------------------------
__device__ void prep_body(const float* __restrict__ S, char* pool)
{
    PrepSm& P = *(PrepSm*)pool;
    const int t    = threadIdx.x;
    const int lane = t & 31;
    const int wid  = t >> 5;

    #pragma unroll 4
    for (int i = 0; i < NCOMBO; i++)
        P.s8[i * NSTRUCT + t] = (S[i * NSTRUCT + t] != 0.0f) ? 1 : 0;
    __syncthreads();

    if (t < NCOMBO) {
        int c = 0;
        for (int j = 0; j < NSTRUCT; j++) c += P.s8[t * NSTRUCT + j];
        P.scnt[t] = c;
    }
    __syncthreads();
    if (t == 0) {
        int acc = 0;
        for (int i = 0; i < NCOMBO; i++) {
            g_row_ptr[i] = acc; P.srp[i] = acc;
            acc += (P.scnt[i] + 1) & ~1;
        }
        g_row_ptr[NCOMBO] = acc; P.srp[NCOMBO] = acc;
    }
    __syncthreads();
    if (t < NCOMBO) {
        int p = P.srp[t];
        const int e = P.srp[t + 1];
        for (int j = 0; j < NSTRUCT; j++)
            if (P.s8[t * NSTRUCT + j]) g_csr_cols[p++] = (unsigned short)j;
        while (p < e) g_csr_cols[p++] = (unsigned short)NSTRUCT;
    }

    int cc = 0;
    for (int i = 0; i < NCOMBO; i++) cc += P.s8[i * NSTRUCT + t];
    const int pc = (cc + 1) & ~1;
    int incl = pc;
    #pragma unroll
    for (int o = 1; o < 32; o <<= 1) {
        int nbr = __shfl_up_sync(0xffffffffu, incl, o);
        if (lane >= o) incl += nbr;
    }
    if (lane == 31) P.wtot[wid] = incl;
    __syncthreads();
    if (t < 16) {
        int xv = P.wtot[t];
        #pragma unroll
        for (int o = 1; o < 16; o <<= 1) {
            int nbr = __shfl_up_sync(0x0000ffffu, xv, o);
            if (t >= o) xv += nbr;
        }
        P.wtot[t] = xv;
    }
    __syncthreads();
    {
        int base = (wid > 0) ? P.wtot[wid - 1] : 0;
        int cend = base + incl;
        g_col_ptr[t + 1] = cend; P.scp[t + 1] = cend;
        if (t == 0) { g_col_ptr[0] = 0; P.scp[0] = 0; }
        int p = cend - pc;
        for (int i = 0; i < NCOMBO; i++)
            if (P.s8[i * NSTRUCT + t]) g_csc_rows[p++] = (unsigned short)i;
        while (p < cend) g_csc_rows[p++] = (unsigned short)NCOMBO;
    }
    __syncthreads();

    unsigned short* sl_csr = (unsigned short*)P.s8;
    unsigned short* sl_csc = (unsigned short*)(P.s8 + 16384);
    const int nr = P.srp[NCOMBO];
    const int nc = P.scp[NSTRUCT];
    const bool ok = (nr <= 8192) && (nc <= 8192);
    if (ok) {
        for (int p = t; p < nr; p += 512) sl_csr[p] = g_csr_cols[p];
        for (int p = t; p < nc; p += 512) sl_csc[p] = g_csc_rows[p];
    }
    __syncthreads();
    const unsigned short* __restrict__ pcsr = ok ? sl_csr : g_csr_cols;
    const unsigned short* __restrict__ pcsc = ok ? sl_csc : g_csc_rows;

    P.v[t] = 1.0f / sqrtf((float)NSTRUCT);
    if (t == 0) { P.v[NSTRUCT] = 0.f; P.sv[NCOMBO] = 0.f; }
    __syncthreads();
    for (int step = 0; step < 30; step++) {
        if (t < NCOMBO) {
            float a = 0.f;
            const int e = P.srp[t + 1];
            for (int p = P.srp[t]; p < e; p++) a += P.v[pcsr[p]];
            P.sv[t] = a;
        }
        __syncthreads();
        float w = P.v[t];
        {
            const int e = P.scp[t + 1];
            for (int p = P.scp[t]; p < e; p++) w += P.sv[pcsc[p]];
        }
        float sq = w * w;
        #pragma unroll
        for (int o = 16; o > 0; o >>= 1) sq += __shfl_xor_sync(0xffffffffu, sq, o);
        if (lane == 0) P.red[wid] = sq;
        __syncthreads();
        if (t == 0) {
            float s = 0.f;
            #pragma unroll
            for (int i = 0; i < 16; i++) s += P.red[i];
            P.red[0] = sqrtf(s);
        }
        __syncthreads();
        P.v[t] = w / P.red[0];
        __syncthreads();
    }
    if (t < NCOMBO) {
        float a = 0.f;
        const int e = P.srp[t + 1];
        for (int p = P.srp[t]; p < e; p++) a += P.v[pcsr[p]];
        P.sv[t] = a;
    }
    __syncthreads();
    {
        float w = P.v[t];
        const int e = P.scp[t + 1];
        for (int p = P.scp[t]; p < e; p++) w += P.sv[pcsc[p]];
        float sq = P.v[t] * w;
        #pragma unroll
        for (int o = 16; o > 0; o >>= 1) sq += __shfl_xor_sync(0xffffffffu, sq, o);
        if (lane == 0) P.red[wid] = sq;
        __syncthreads();
        if (t == 0) {
            float s = 0.f;
            #pragma unroll
            for (int i = 0; i < 16; i++) s += P.red[i];
            g_tau = 0.9f / sqrtf(s);
        }
    }
}

// ---------------- sgemm_v3x2 body: transposed-A smem + fma.rn.f32x2 -------
template<int BM, int BN, int THREADS, int K, int N>
__device__ void sgemm_v3_body(
    const float* __restrict__ A, const float* __restrict__ B,
    const float* __restrict__ bias, float* __restrict__ C,
    int m0, int n0, char* pool)
{
    constexpr int KC = 16;
    constexpr int CA4 = BM * KC / 4 / THREADS;
    constexpr int CB  = KC * BN / 4;
    constexpr int NSTAGE = K / KC;
    GemmSm& G = *(GemmSm*)pool;

    const int tid = threadIdx.x;
    constexpr int TX = BN / 8;
    const int tx = tid % TX;
    const int ty = tid / TX;
    const int rowA = ty * 4;
    const int colA = tx * 4;

    u64 acc2[8][4];
    #pragma unroll
    for (int i = 0; i < 8; i++)
        #pragma unroll
        for (int j = 0; j < 4; j++) acc2[i][j] = 0ull;

    int am[CA4], akq[CA4];
    #pragma unroll
    for (int q = 0; q < CA4; q++) {
        const int c = tid + q * THREADS;
        am[q]  = c >> 2;
        akq[q] = (c & 3) * 4;
    }

    float4 areg[CA4];
    #pragma unroll
    for (int q = 0; q < CA4; q++)
        areg[q] = *(const float4*)(A + (size_t)(m0 + am[q]) * K + akq[q]);
    #pragma unroll
    for (int c = tid; c < CB; c += THREADS) {
        const int kr = c / (BN / 4);
        const int nq = (c % (BN / 4)) * 4;
        cp_async16(&G.Bs[0][kr][nq], B + (size_t)kr * N + n0 + nq);
    }
    cp_commit();

    for (int s = 0; s < NSTAGE; s++) {
        const int buf = s & 1;
        #pragma unroll
        for (int q = 0; q < CA4; q++) {
            G.As[buf][akq[q] + 0][am[q]] = areg[q].x;
            G.As[buf][akq[q] + 1][am[q]] = areg[q].y;
            G.As[buf][akq[q] + 2][am[q]] = areg[q].z;
            G.As[buf][akq[q] + 3][am[q]] = areg[q].w;
        }
        if (s + 1 < NSTAGE) {
            const int k0 = (s + 1) * KC;
            const int nb = (s + 1) & 1;
            #pragma unroll
            for (int c = tid; c < CB; c += THREADS) {
                const int kr = c / (BN / 4);
                const int nq = (c % (BN / 4)) * 4;
                cp_async16(&G.Bs[nb][kr][nq], B + (size_t)(k0 + kr) * N + n0 + nq);
            }
            cp_commit();
            cp_wait<1>();
        } else {
            cp_wait<0>();
        }
        __syncthreads();
        if (s + 1 < NSTAGE) {
            const int k0 = (s + 1) * KC;
            #pragma unroll
            for (int q = 0; q < CA4; q++)
                areg[q] = *(const float4*)(A + (size_t)(m0 + am[q]) * K + k0 + akq[q]);
        }
        #pragma unroll
        for (int kk = 0; kk < KC; kk++) {
            float fa[8];
            *(float4*)&fa[0] = *(const float4*)&G.As[buf][kk][rowA];
            *(float4*)&fa[4] = *(const float4*)&G.As[buf][kk][rowA + BM / 2];
            const ulonglong2 b0 = *(const ulonglong2*)&G.Bs[buf][kk][colA];
            const ulonglong2 b1 = *(const ulonglong2*)&G.Bs[buf][kk][colA + BN / 2];
            u64 bp[4];
            bp[0] = b0.x; bp[1] = b0.y; bp[2] = b1.x; bp[3] = b1.y;
            u64 ap[8];
            #pragma unroll
            for (int i = 0; i < 8; i++) ap[i] = packdup(fa[i]);
            #pragma unroll
            for (int i = 0; i < 8; i++)
                #pragma unroll
                for (int jp = 0; jp < 4; jp++)
                    fma2(acc2[i][jp], ap[i], bp[jp]);
        }
        __syncthreads();
    }

    float4 bl = *(const float4*)(bias + n0 + colA);
    float4 bh = *(const float4*)(bias + n0 + colA + BN / 2);
    #pragma unroll
    for (int half = 0; half < 2; half++) {
        #pragma unroll
        for (int i = 0; i < 4; i++) {
            const int m  = m0 + rowA + half * (BM / 2) + i;
            const int ai = half * 4 + i;
            const float2 p0 = unpack2(acc2[ai][0]);
            const float2 p1 = unpack2(acc2[ai][1]);
            const float2 p2 = unpack2(acc2[ai][2]);
            const float2 p3 = unpack2(acc2[ai][3]);
            float4 o;
            o.x = fmaxf(p0.x + bl.x, 0.f);
            o.y = fmaxf(p0.y + bl.y, 0.f);
            o.z = fmaxf(p1.x + bl.z, 0.f);
            o.w = fmaxf(p1.y + bl.w, 0.f);
            *(float4*)(C + (size_t)m * N + n0 + colA) = o;
            float4 p;
            p.x = fmaxf(p2.x + bh.x, 0.f);
            p.y = fmaxf(p2.y + bh.y, 0.f);
            p.z = fmaxf(p3.x + bh.z, 0.f);
            p.w = fmaxf(p3.y + bh.w, 0.f);
            *(float4*)(C + (size_t)m * N + n0 + colA + BN / 2) = p;
        }
    }
}

// ---------------- fused prep + gemm1 (grid 129 x 512 threads) -------------
__global__ __launch_bounds__(512, 1) void fused1_kernel(
    const float* __restrict__ X, const float* __restrict__ W1,
    const float* __restrict__ b1, const float* __restrict__ S)
{
    __shared__ __align__(16) char pool[sizeof(PrepSm) > sizeof(GemmSm)
                                       ? sizeof(PrepSm) : sizeof(GemmSm)];
    if (blockIdx.x == 128) {
        prep_body(S, pool);
        return;
    }
    if (threadIdx.x >= 256) return;
    const int n0 = (blockIdx.x & 7) * 128;
    const int m0 = (blockIdx.x >> 3) * 128;
    sgemm_v3_body<128, 128, 256, NCOMBO, NHID>(X, W1, b1, g_C1, m0, n0, pool);
}

__global__ __launch_bounds__(256, 2) void gemm2_kernel(
    const float* __restrict__ W2, const float* __restrict__ b2)
{
    __shared__ __align__(16) char pool[sizeof(GemmSm)];
    sgemm_v3_body<128, 128, 256, NHID, NHID>(g_C1, W2, b2, g_C2,
                                             blockIdx.y * 128, blockIdx.x * 128, pool);
}

// ---------------- gemm3: v3h + f32x2 (BM=64, 256 threads) -----------------
__global__ __launch_bounds__(256, 2) void gemm3_kernel(
    const float* __restrict__ W3, const float* __restrict__ b3)
{
    constexpr int BM = 64, BN = 128, TH = 256, KC = 16, K = NHID, N = NSTRUCT;
    constexpr int CB = KC * BN / 4;
    constexpr int NSTAGE = K / KC;
    __shared__ float As[2][KC][BM];
    __shared__ float Bs[2][KC][BN];
    const float* A = g_C2;
    const int tid = threadIdx.x;
    const int m0 = blockIdx.y * BM, n0 = blockIdx.x * BN;
    const int tx = tid & 15;
    const int ty = tid >> 4;
    const int rowA = ty * 2;
    const int colA = tx * 4;

    u64 acc2[4][4];
    #pragma unroll
    for (int i = 0; i < 4; i++)
        #pragma unroll
        for (int j = 0; j < 4; j++) acc2[i][j] = 0ull;

    const int am  = tid >> 2;
    const int akq = (tid & 3) * 4;

    float4 areg = *(const float4*)(A + (size_t)(m0 + am) * K + akq);
    #pragma unroll
    for (int c = tid; c < CB; c += TH) {
        const int kr = c / 32;
        const int nq = (c % 32) * 4;
        cp_async16(&Bs[0][kr][nq], W3 + (size_t)kr * N + n0 + nq);
    }
    cp_commit();

    for (int s = 0; s < NSTAGE; s++) {
        const int buf = s & 1;
        As[buf][akq + 0][am] = areg.x;
        As[buf][akq + 1][am] = areg.y;
        As[buf][akq + 2][am] = areg.z;
        As[buf][akq + 3][am] = areg.w;
        if (s + 1 < NSTAGE) {
            const int k0 = (s + 1) * KC;
            const int nb = (s + 1) & 1;
            #pragma unroll
            for (int c = tid; c < CB; c += TH) {
                const int kr = c / 32;
                const int nq = (c % 32) * 4;
                cp_async16(&Bs[nb][kr][nq], W3 + (size_t)(k0 + kr) * N + n0 + nq);
            }
            cp_commit();
            cp_wait<1>();
        } else {
            cp_wait<0>();
        }
        __syncthreads();
        if (s + 1 < NSTAGE) {
            const int k0 = (s + 1) * KC;
            areg = *(const float4*)(A + (size_t)(m0 + am) * K + k0 + akq);
        }
        #pragma unroll
        for (int kk = 0; kk < KC; kk++) {
            float fa[4];
            *(float2*)&fa[0] = *(const float2*)&As[buf][kk][rowA];
            *(float2*)&fa[2] = *(const float2*)&As[buf][kk][rowA + 32];
            const ulonglong2 b0 = *(const ulonglong2*)&Bs[buf][kk][colA];
            const ulonglong2 b1 = *(const ulonglong2*)&Bs[buf][kk][colA + 64];
            u64 bp[4];
            bp[0] = b0.x; bp[1] = b0.y; bp[2] = b1.x; bp[3] = b1.y;
            u64 ap[4];
            #pragma unroll
            for (int i = 0; i < 4; i++) ap[i] = packdup(fa[i]);
            #pragma unroll
            for (int i = 0; i < 4; i++)
                #pragma unroll
                for (int jp = 0; jp < 4; jp++)
                    fma2(acc2[i][jp], ap[i], bp[jp]);
        }
        __syncthreads();
    }

    float4 bl = *(const float4*)(b3 + n0 + colA);
    float4 bh = *(const float4*)(b3 + n0 + colA + 64);
    #pragma unroll
    for (int half = 0; half < 2; half++) {
        #pragma unroll
        for (int i = 0; i < 2; i++) {
            const int m  = m0 + half * 32 + rowA + i;
            const int ai = half * 2 + i;
            const float2 p0 = unpack2(acc2[ai][0]);
            const float2 p1 = unpack2(acc2[ai][1]);
            const float2 p2 = unpack2(acc2[ai][2]);
            const float2 p3 = unpack2(acc2[ai][3]);
            float4 o;
            o.x = fmaxf(p0.x + bl.x, 0.f);
            o.y = fmaxf(p0.y + bl.y, 0.f);
            o.z = fmaxf(p1.x + bl.z, 0.f);
            o.w = fmaxf(p1.y + bl.w, 0.f);
            *(float4*)(g_Z + (size_t)m * N + n0 + colA) = o;
            float4 p;
            p.x = fmaxf(p2.x + bh.x, 0.f);
            p.y = fmaxf(p2.y + bh.y, 0.f);
            p.z = fmaxf(p3.x + bh.z, 0.f);
            p.w = fmaxf(p3.y + bh.w, 0.f);
            *(float4*)(g_Z + (size_t)m * N + n0 + colA + 64) = p;
        }
    }
}

// ---------------- PDHG v9: v8 + staged scale reduction (unchanged) --------
#define V8_XBAR  0
#define V8_YHEAD (V8_XBAR + (NSTRUCT + 1) * 16 * 4)
#define V8_CSR   (V8_YHEAD + (NCOMBO + 1) * 16 * 4)
#define V8_CSC   (V8_CSR + SMNNZ * 2)
#define V8_RP    (V8_CSC + SMNNZ * 2)
#define V8_CP    (V8_RP + (NCOMBO + 2) * 4)
#define V8_RED   ((V8_CP + (NSTRUCT + 2) * 4 + 15) & ~15)
#define V8_SCALE (V8_RED + 16 * 8 * 8)
#define V8_SMEM  (V8_SCALE + 8 * 8)

__global__ __launch_bounds__(512, 1) void pdhg_kernel(
    const float* __restrict__ Xg, float* __restrict__ out)
{
    extern __shared__ char smem[];
    float*   s_xbar  = (float*)(smem + V8_XBAR);
    float*   s_yhead = (float*)(smem + V8_YHEAD);
    ushort2* s_csr2  = (ushort2*)(smem + V8_CSR);
    ushort2* s_csc2  = (ushort2*)(smem + V8_CSC);
    int*     s_rp    = (int*)(smem + V8_RP);
    int*     s_cp    = (int*)(smem + V8_CP);
    float2*  s_red   = (float2*)(smem + V8_RED);
    float2*  s_scale = (float2*)(smem + V8_SCALE);

    const int tid = threadIdx.x;
    const int b4  = tid & 7;
    const int dl  = tid >> 3;
    const int wid = tid >> 5;
    const int r0  = blockIdx.x * 16 + b4 * 2;
    const int bo  = b4 * 2;

    for (int p = tid; p < NCOMBO + 1;  p += 512) s_rp[p] = g_row_ptr[p];
    for (int p = tid; p < NSTRUCT + 1; p += 512) s_cp[p] = g_col_ptr[p];
    for (int p = tid; p < (NSTRUCT + 1) * 16; p += 512) s_xbar[p] = 0.f;
    for (int p = tid; p < (NCOMBO + 1) * 16;  p += 512) s_yhead[p] = 0.f;
    __syncthreads();
    const int nnzr = s_rp[NCOMBO];
    const int nnzc = s_cp[NSTRUCT];
    const bool fits = (nnzr <= SMNNZ) && (nnzc <= SMNNZ);
    if (fits) {
        const ushort2* gr = (const ushort2*)g_csr_cols;
        const ushort2* gc = (const ushort2*)g_csc_rows;
        for (int p = tid; p < nnzr / 2; p += 512) s_csr2[p] = gr[p];
        for (int p = tid; p < nnzc / 2; p += 512) s_csc2[p] = gc[p];
    }
    const ushort2* __restrict__ csr2 = fits ? s_csr2 : (const ushort2*)g_csr_cols;
    const ushort2* __restrict__ csc2 = fits ? s_csc2 : (const ushort2*)g_csc_rows;
    const float tau = g_tau;

    float2 x[8], z[8], yt[8], xb[8];
    #pragma unroll
    for (int k = 0; k < 8; k++) {
        const int j = k * 64 + dl;
        z[k].x = g_Z[(size_t)r0 * NSTRUCT + j];
        z[k].y = g_Z[(size_t)(r0 + 1) * NSTRUCT + j];
        x[k]  = make_float2(0.f, 0.f);
        yt[k] = make_float2(0.f, 0.f);
        xb[k] = make_float2(0.f, 0.f);
    }
    const int i = dl;
    float2 Bv = make_float2(Xg[(size_t)r0 * NCOMBO + i],
                            Xg[(size_t)(r0 + 1) * NCOMBO + i]);
    float2 yh = make_float2(0.f, 0.f);
    const int rs2 = s_rp[i] >> 1, re2 = s_rp[i + 1] >> 1;
    __syncthreads();

    for (int it = 0; it < NITER; it++) {
        // ---- phase A: y-head (Kx over packed CSR) + y-tail ----
        float a0x = 0.f, a0y = 0.f, a1x = 0.f, a1y = 0.f;
        #pragma unroll 2
        for (int p = rs2; p < re2; p++) {
            const ushort2 c = csr2[p];
            const float2 v0 = *(const float2*)&s_xbar[c.x * 16 + bo];
            const float2 v1 = *(const float2*)&s_xbar[c.y * 16 + bo];
            a0x += v0.x; a0y += v0.y;
            a1x += v1.x; a1y += v1.y;
        }
        yh.x = fmaxf(yh.x + tau * ((a0x + a1x) - Bv.x), 0.f);
        yh.y = fmaxf(yh.y + tau * ((a0y + a1y) - Bv.y), 0.f);
        *(float2*)&s_yhead[i * 16 + bo] = yh;
        #pragma unroll
        for (int k = 0; k < 8; k++) {
            yt[k].x = fmaxf(yt[k].x - tau * xb[k].x, 0.f);
            yt[k].y = fmaxf(yt[k].y - tau * xb[k].y, 0.f);
        }
        __syncthreads();

        // ---- phase B: KTy over packed CSC + prox residual ----
        float2 d[8];
        float ssx = 0.f, ssy = 0.f;
        #pragma unroll
        for (int k = 0; k < 8; k++) {
            const int j = k * 64 + dl;
            float t0x = -yt[k].x, t0y = -yt[k].y;
            float t1x = 0.f, t1y = 0.f;
            const int ps2 = s_cp[j] >> 1, pe2 = s_cp[j + 1] >> 1;
            for (int p = ps2; p < pe2; p++) {
                const ushort2 rr = csc2[p];
                const float2 va = *(const float2*)&s_yhead[rr.x * 16 + bo];
                const float2 vb = *(const float2*)&s_yhead[rr.y * 16 + bo];
                t0x += va.x; t0y += va.y;
                t1x += vb.x; t1y += vb.y;
            }
            const float dx = x[k].x - tau * (t0x + t1x) + tau - z[k].x;
            const float dy = x[k].y - tau * (t0y + t1y) + tau - z[k].y;
            d[k] = make_float2(dx, dy);
            ssx += dx * dx;
            ssy += dy * dy;
        }
        ssx += __shfl_xor_sync(0xffffffffu, ssx, 8);
        ssy += __shfl_xor_sync(0xffffffffu, ssy, 8);
        ssx += __shfl_xor_sync(0xffffffffu, ssx, 16);
        ssy += __shfl_xor_sync(0xffffffffu, ssy, 16);
        if ((tid & 31) < 8) s_red[wid * 8 + b4] = make_float2(ssx, ssy);
        __syncthreads();

        // ---- phase C1: 8 threads compute the 8 scales ----
        if (tid < 8) {
            float totx = 0.f, toty = 0.f;
            #pragma unroll
            for (int w = 0; w < 16; w++) {
                const float2 r = s_red[w * 8 + tid];
                totx += r.x; toty += r.y;
            }
            float2 sc;
            sc.x = fmaxf(1.f - tau / fmaxf(sqrtf(totx), 1e-12f), 0.f);
            sc.y = fmaxf(1.f - tau / fmaxf(sqrtf(toty), 1e-12f), 0.f);
            s_scale[tid] = sc;
        }
        __syncthreads();

        // ---- phase C2: x / xbar update ----
        const float2 sc = s_scale[b4];
        #pragma unroll
        for (int k = 0; k < 8; k++) {
            const float xnx = z[k].x + sc.x * d[k].x;
            const float xny = z[k].y + sc.y * d[k].y;
            const float2 xbn = make_float2(2.f * xnx - x[k].x, 2.f * xny - x[k].y);
            x[k]  = make_float2(xnx, xny);
            xb[k] = xbn;
            *(float2*)&s_xbar[(k * 64 + dl) * 16 + bo] = xbn;
        }
        __syncthreads();
    }

    #pragma unroll
    for (int k = 0; k < 8; k++) {
        const int j = k * 64 + dl;
        out[(size_t)r0 * NSTRUCT + j]       = x[k].x;
        out[(size_t)(r0 + 1) * NSTRUCT + j] = x[k].y;
    }
}

// ---------------- launch -------------------------------------------------
extern "C" void kernel_launch(void* const* d_in, const int* in_sizes, int n_in,
                              void* d_out, int out_size)
{
    const float* X  = (const float*)d_in[0];
    const float* W1 = (const float*)d_in[1];
    const float* b1 = (const float*)d_in[2];
    const float* W2 = (const float*)d_in[3];
    const float* b2 = (const float*)d_in[4];
    const float* W3 = (const float*)d_in[5];
    const float* b3 = (const float*)d_in[6];
    const float* S  = (const float*)d_in[7];
    float* out = (float*)d_out;

    cudaFuncSetAttribute(pdhg_kernel,
                         cudaFuncAttributeMaxDynamicSharedMemorySize, V8_SMEM);

    fused1_kernel<<<129, 512>>>(X, W1, b1, S);
    gemm2_kernel<<<dim3(NHID / 128,    NB_ROWS / 128), 256>>>(W2, b2);
    gemm3_kernel<<<dim3(NSTRUCT / 128, NB_ROWS / 64),  256>>>(W3, b3);

    pdhg_kernel<<<NB_ROWS / 16, 512, V8_SMEM>>>(X, out);
}